// round 3
// baseline (speedup 1.0000x reference)
#include <cuda_runtime.h>

#define N_NODES 50000
#define N_EDGES 800000
#define ET (N_EDGES + N_NODES)   // edges + self loops
#define F_IN 128
#define HEADS 4
#define HID 64
#define HH (HEADS*HID)           // 256
#define NEG 0.2f

// -------- device scratch (static: no allocation allowed) --------
__device__ __align__(16) float    g_h1[N_NODES*HH];     // layer1 features (x@W1)
__device__ __align__(16) float    g_acc1[N_NODES*HH];   // layer1 numerator / activated out
__device__ __align__(16) float    g_as1[N_NODES*HEADS];
__device__ __align__(16) float    g_ad1[N_NODES*HEADS];
__device__ __align__(16) float    g_z1[N_NODES*HEADS];
__device__ __align__(16) unsigned g_m1[N_NODES*HEADS];
__device__ __align__(16) int      g_src[N_EDGES];
__device__ __align__(16) int      g_dst[N_EDGES];
__device__ __align__(16) float    g_h2[N_NODES*2];
__device__ __align__(16) float    g_as2[N_NODES];
__device__ __align__(16) float    g_ad2[N_NODES];
__device__ __align__(16) float    g_z2[N_NODES];
__device__ __align__(16) unsigned g_m2[N_NODES];
__device__ __align__(16) float    g_acc2[N_NODES*2];
__device__ int g_fmt64;   // 1 if edge_index buffer is int64, 0 if int32

__device__ __forceinline__ float lrelu(float x) { return x > 0.f ? x : NEG * x; }

// monotonic float<->uint map for atomicMax on floats (handles negatives)
__device__ __forceinline__ unsigned fenc(float f) {
    unsigned u = __float_as_uint(f);
    return (u & 0x80000000u) ? ~u : (u | 0x80000000u);
}
__device__ __forceinline__ float fdec(unsigned k) {
    return (k & 0x80000000u) ? __uint_as_float(k ^ 0x80000000u)
                             : __uint_as_float(~k);
}

__device__ __forceinline__ void red_add_v4(float* addr, float a, float b, float c, float d) {
    asm volatile("red.global.add.v4.f32 [%0], {%1, %2, %3, %4};"
                 :: "l"(addr), "f"(a), "f"(b), "f"(c), "f"(d) : "memory");
}

// -------- detect int64 vs int32 edge_index layout --------
// Reads only the first 2048 int32 words — in-bounds for either dtype.
// int64 layout: words at odd indices are high words of values < 50000 -> all 0.
// int32 layout: words at odd indices are edge indices -> almost surely nonzero.
__global__ void k_detect(const int* __restrict__ ei32) {
    __shared__ int nz;
    if (threadIdx.x == 0) nz = 0;
    __syncthreads();
    int c = 0;
    for (int i = threadIdx.x; i < 1024; i += blockDim.x)
        if (ei32[2*i + 1] != 0) c++;
    atomicAdd(&nz, c);
    __syncthreads();
    if (threadIdx.x == 0) g_fmt64 = (nz == 0) ? 1 : 0;
}

// -------- init: zero accumulators, convert edges to int32 --------
__global__ void k_init(const void* __restrict__ ei) {
    int i = blockIdx.x * blockDim.x + threadIdx.x;
    if (i < N_NODES * HH) g_acc1[i] = 0.f;
    if (i < N_EDGES) {
        if (g_fmt64) {
            const long long* e = (const long long*)ei;
            g_src[i] = (int)e[i];
            g_dst[i] = (int)e[N_EDGES + i];
        } else {
            const int* e = (const int*)ei;
            g_src[i] = e[i];
            g_dst[i] = e[N_EDGES + i];
        }
    }
    if (i < N_NODES * HEADS) { g_z1[i] = 0.f; g_m1[i] = 0u; }
    if (i < N_NODES) {
        g_z2[i] = 0.f; g_m2[i] = 0u;
        g_acc2[2*i] = 0.f; g_acc2[2*i+1] = 0.f;
    }
}

// -------- SGEMM: C[M,256] = A[M,128] @ B[128,256], C = g_h1 --------
#define BM 64
#define BN 64
#define BK 16
__global__ void k_sgemm(const float* __restrict__ A, const float* __restrict__ B, int M) {
    __shared__ float As[BK][BM];
    __shared__ float Bs[BK][BN];
    const int t  = threadIdx.x;          // 256 threads
    const int ty = t >> 4;               // 0..15
    const int tx = t & 15;               // 0..15
    const int bm = blockIdx.x * BM;
    const int bn = blockIdx.y * BN;

    float acc[4][4];
#pragma unroll
    for (int i = 0; i < 4; i++)
#pragma unroll
        for (int j = 0; j < 4; j++) acc[i][j] = 0.f;

    for (int kt = 0; kt < F_IN; kt += BK) {
        {
            int row = t >> 2;            // 0..63
            int kv  = t & 3;             // 0..3 (float4 along k)
            float4 a4 = make_float4(0.f, 0.f, 0.f, 0.f);
            int ar = bm + row;
            if (ar < M) a4 = *(const float4*)(A + (size_t)ar * F_IN + kt + kv * 4);
            As[kv*4+0][row] = a4.x;
            As[kv*4+1][row] = a4.y;
            As[kv*4+2][row] = a4.z;
            As[kv*4+3][row] = a4.w;
        }
        {
            int kr = t >> 4;             // 0..15
            int cv = t & 15;             // 0..15
            float4 b4 = *(const float4*)(B + (size_t)(kt + kr) * HH + bn + cv * 4);
            *(float4*)&Bs[kr][cv*4] = b4;
        }
        __syncthreads();
#pragma unroll
        for (int k = 0; k < BK; k++) {
            float a0 = As[k][ty*4+0], a1 = As[k][ty*4+1];
            float a2 = As[k][ty*4+2], a3 = As[k][ty*4+3];
            float b0 = Bs[k][tx*4+0], b1 = Bs[k][tx*4+1];
            float b2 = Bs[k][tx*4+2], b3 = Bs[k][tx*4+3];
            acc[0][0] += a0*b0; acc[0][1] += a0*b1; acc[0][2] += a0*b2; acc[0][3] += a0*b3;
            acc[1][0] += a1*b0; acc[1][1] += a1*b1; acc[1][2] += a1*b2; acc[1][3] += a1*b3;
            acc[2][0] += a2*b0; acc[2][1] += a2*b1; acc[2][2] += a2*b2; acc[2][3] += a2*b3;
            acc[3][0] += a3*b0; acc[3][1] += a3*b1; acc[3][2] += a3*b2; acc[3][3] += a3*b3;
        }
        __syncthreads();
    }
#pragma unroll
    for (int i = 0; i < 4; i++) {
        int row = bm + ty*4 + i;
        if (row < M) {
#pragma unroll
            for (int j = 0; j < 4; j++)
                g_h1[(size_t)row * HH + bn + tx*4 + j] = acc[i][j];
        }
    }
}

// -------- per-node attention dots --------
__global__ void k_attdots1(const float* __restrict__ attS, const float* __restrict__ attD) {
    int w    = (blockIdx.x * blockDim.x + threadIdx.x) >> 5;
    int lane = threadIdx.x & 31;
    if (w >= N_NODES) return;
    const float4* hv = (const float4*)(g_h1 + (size_t)w * HH);
    float4 v0 = hv[lane];        // channels lane*4 .. +3      (heads 0/1)
    float4 v1 = hv[32 + lane];   // channels 128+lane*4 .. +3  (heads 2/3)
    const float4* aS = (const float4*)attS;
    const float4* aD = (const float4*)attD;
    float4 s0 = aS[lane], s1 = aS[32 + lane];
    float4 d0 = aD[lane], d1 = aD[32 + lane];
    float ps0 = v0.x*s0.x + v0.y*s0.y + v0.z*s0.z + v0.w*s0.w;
    float ps1 = v1.x*s1.x + v1.y*s1.y + v1.z*s1.z + v1.w*s1.w;
    float pd0 = v0.x*d0.x + v0.y*d0.y + v0.z*d0.z + v0.w*d0.w;
    float pd1 = v1.x*d1.x + v1.y*d1.y + v1.z*d1.z + v1.w*d1.w;
#pragma unroll
    for (int o = 1; o < 16; o <<= 1) {
        ps0 += __shfl_xor_sync(0xffffffffu, ps0, o);
        ps1 += __shfl_xor_sync(0xffffffffu, ps1, o);
        pd0 += __shfl_xor_sync(0xffffffffu, pd0, o);
        pd1 += __shfl_xor_sync(0xffffffffu, pd1, o);
    }
    if ((lane & 15) == 0) {
        int h0 = lane >> 4;          // 0 or 1
        g_as1[w*4 + h0]     = ps0;
        g_as1[w*4 + h0 + 2] = ps1;
        g_ad1[w*4 + h0]     = pd0;
        g_ad1[w*4 + h0 + 2] = pd1;
    }
}

// -------- layer1 segment max (edge-parallel, incl self-loops) --------
__global__ void k_edge_max1() {
    int i = blockIdx.x * blockDim.x + threadIdx.x;
    if (i >= ET) return;
    int s, d;
    if (i < N_EDGES) { s = g_src[i]; d = g_dst[i]; }
    else             { s = d = i - N_EDGES; }
    float4 as = *(const float4*)(g_as1 + s*4);
    float4 ad = *(const float4*)(g_ad1 + d*4);
    atomicMax(&g_m1[d*4+0], fenc(lrelu(as.x + ad.x)));
    atomicMax(&g_m1[d*4+1], fenc(lrelu(as.y + ad.y)));
    atomicMax(&g_m1[d*4+2], fenc(lrelu(as.z + ad.z)));
    atomicMax(&g_m1[d*4+3], fenc(lrelu(as.w + ad.w)));
}

// -------- layer1: z += exp(e-m); acc += exp(e-m)*h1[src]  (warp per edge) --------
__global__ void k_edge_acc1() {
    int w    = (blockIdx.x * blockDim.x + threadIdx.x) >> 5;
    int lane = threadIdx.x & 31;
    if (w >= ET) return;
    int s, d;
    if (w < N_EDGES) { s = g_src[w]; d = g_dst[w]; }
    else             { s = d = w - N_EDGES; }
    float4 as = *(const float4*)(g_as1 + s*4);
    float4 ad = *(const float4*)(g_ad1 + d*4);
    uint4  mk = *(const uint4*)(g_m1 + d*4);
    float ex0 = __expf(lrelu(as.x + ad.x) - fdec(mk.x));
    float ex1 = __expf(lrelu(as.y + ad.y) - fdec(mk.y));
    float ex2 = __expf(lrelu(as.z + ad.z) - fdec(mk.z));
    float ex3 = __expf(lrelu(as.w + ad.w) - fdec(mk.w));
    if (lane < 4) {
        float zv = lane == 0 ? ex0 : lane == 1 ? ex1 : lane == 2 ? ex2 : ex3;
        atomicAdd(&g_z1[d*4 + lane], zv);
    }
    float m0  = (lane < 16) ? ex0 : ex1;
    float m1v = (lane < 16) ? ex2 : ex3;
    const float4* hv = (const float4*)(g_h1 + (size_t)s * HH);
    float4 v0 = hv[lane];
    float4 v1 = hv[32 + lane];
    float* base = g_acc1 + (size_t)d * HH;
    red_add_v4(base + lane*4,        m0*v0.x,  m0*v0.y,  m0*v0.z,  m0*v0.w);
    red_add_v4(base + 128 + lane*4,  m1v*v1.x, m1v*v1.y, m1v*v1.z, m1v*v1.w);
}

// -------- layer1 normalize + bias + ELU (in place on g_acc1) --------
__global__ void k_norm1(const float* __restrict__ b1) {
    int i = blockIdx.x * blockDim.x + threadIdx.x;
    if (i >= N_NODES * HH) return;
    int n = i >> 8, c = i & 255;
    float z = g_z1[n*4 + (c >> 6)];
    float v = g_acc1[i] / z + b1[c];
    g_acc1[i] = v > 0.f ? v : (expf(v) - 1.f);
}

// -------- layer2 features: h2 = hact @ W2 (256->2), plus attention dots --------
__global__ void k_gemv2(const float* __restrict__ W2,
                        const float* __restrict__ attS2, const float* __restrict__ attD2) {
    int w    = (blockIdx.x * blockDim.x + threadIdx.x) >> 5;
    int lane = threadIdx.x & 31;
    if (w >= N_NODES) return;
    const float4* hv = (const float4*)(g_acc1 + (size_t)w * HH);
    float4 v0 = hv[lane];
    float4 v1 = hv[32 + lane];
    const float2* Wv = (const float2*)W2;     // [256] float2
    float s0 = 0.f, s1 = 0.f;
    int c0 = lane * 4;
    float2 w0;
    w0 = Wv[c0+0];      s0 += v0.x*w0.x; s1 += v0.x*w0.y;
    w0 = Wv[c0+1];      s0 += v0.y*w0.x; s1 += v0.y*w0.y;
    w0 = Wv[c0+2];      s0 += v0.z*w0.x; s1 += v0.z*w0.y;
    w0 = Wv[c0+3];      s0 += v0.w*w0.x; s1 += v0.w*w0.y;
    w0 = Wv[128+c0+0];  s0 += v1.x*w0.x; s1 += v1.x*w0.y;
    w0 = Wv[128+c0+1];  s0 += v1.y*w0.x; s1 += v1.y*w0.y;
    w0 = Wv[128+c0+2];  s0 += v1.z*w0.x; s1 += v1.z*w0.y;
    w0 = Wv[128+c0+3];  s0 += v1.w*w0.x; s1 += v1.w*w0.y;
#pragma unroll
    for (int o = 1; o < 32; o <<= 1) {
        s0 += __shfl_xor_sync(0xffffffffu, s0, o);
        s1 += __shfl_xor_sync(0xffffffffu, s1, o);
    }
    if (lane == 0) {
        g_h2[w*2]   = s0;
        g_h2[w*2+1] = s1;
        g_as2[w] = s0*attS2[0] + s1*attS2[1];
        g_ad2[w] = s0*attD2[0] + s1*attD2[1];
    }
}

__global__ void k_edge_max2() {
    int i = blockIdx.x * blockDim.x + threadIdx.x;
    if (i >= ET) return;
    int s, d;
    if (i < N_EDGES) { s = g_src[i]; d = g_dst[i]; }
    else             { s = d = i - N_EDGES; }
    atomicMax(&g_m2[d], fenc(lrelu(g_as2[s] + g_ad2[d])));
}

__global__ void k_edge_acc2() {
    int i = blockIdx.x * blockDim.x + threadIdx.x;
    if (i >= ET) return;
    int s, d;
    if (i < N_EDGES) { s = g_src[i]; d = g_dst[i]; }
    else             { s = d = i - N_EDGES; }
    float e  = lrelu(g_as2[s] + g_ad2[d]);
    float ex = __expf(e - fdec(g_m2[d]));
    atomicAdd(&g_z2[d], ex);
    atomicAdd(&g_acc2[d*2],   ex * g_h2[s*2]);
    atomicAdd(&g_acc2[d*2+1], ex * g_h2[s*2+1]);
}

__global__ void k_final(float* __restrict__ out, const float* __restrict__ b2) {
    int i = blockIdx.x * blockDim.x + threadIdx.x;
    if (i >= N_NODES * 2) return;
    int n = i >> 1, c = i & 1;
    out[i] = g_acc2[i] / g_z2[n] + b2[c];
}

extern "C" void kernel_launch(void* const* d_in, const int* in_sizes, int n_in,
                              void* d_out, int out_size) {
    const float* x    = (const float*)d_in[0];
    const void*  ei   = d_in[1];
    const float* W1   = (const float*)d_in[2];
    const float* aS1  = (const float*)d_in[3];
    const float* aD1  = (const float*)d_in[4];
    const float* b1   = (const float*)d_in[5];
    const float* W2   = (const float*)d_in[6];
    const float* aS2  = (const float*)d_in[7];
    const float* aD2  = (const float*)d_in[8];
    const float* b2   = (const float*)d_in[9];
    float* out = (float*)d_out;

    const int TB = 256;
    k_detect<<<1, 256>>>((const int*)ei);
    k_init<<<(N_NODES*HH + TB - 1) / TB, TB>>>(ei);

    dim3 gg((N_NODES + BM - 1) / BM, HH / BN);
    k_sgemm<<<gg, 256>>>(x, W1, N_NODES);

    k_attdots1<<<(N_NODES*32 + TB - 1) / TB, TB>>>(aS1, aD1);
    k_edge_max1<<<(ET + TB - 1) / TB, TB>>>();
    k_edge_acc1<<<(ET*32 + TB - 1) / TB, TB>>>();
    k_norm1<<<(N_NODES*HH + TB - 1) / TB, TB>>>(b1);

    k_gemv2<<<(N_NODES*32 + TB - 1) / TB, TB>>>(W2, aS2, aD2);
    k_edge_max2<<<(ET + TB - 1) / TB, TB>>>();
    k_edge_acc2<<<(ET + TB - 1) / TB, TB>>>();
    k_final<<<(N_NODES*2 + TB - 1) / TB, TB>>>(out, b2);
}

// round 4
// speedup vs baseline: 1.6345x; 1.6345x over previous
#include <cuda_runtime.h>

#define N_NODES 50000
#define N_EDGES 800000
#define ET (N_EDGES + N_NODES)   // edges + self loops
#define F_IN 128
#define HEADS 4
#define HID 64
#define HH (HEADS*HID)           // 256
#define NEG 0.2f

#define SCAN_BLK 512
#define NB ((N_NODES + SCAN_BLK - 1) / SCAN_BLK)   // 98

// -------- device scratch (static: no allocation allowed) --------
__device__ __align__(16) float    g_h1[N_NODES*HH];     // layer1 features (x@W1)
__device__ __align__(16) float    g_hact[N_NODES*HH];   // layer1 activated output
__device__ __align__(16) float    g_as1[N_NODES*HEADS];
__device__ __align__(16) float    g_ad1[N_NODES*HEADS];
__device__ __align__(16) int      g_src[N_EDGES];
__device__ __align__(16) int      g_dst[N_EDGES];
__device__ __align__(16) int      g_deg[N_NODES];
__device__ __align__(16) int      g_cur[N_NODES];
__device__ __align__(16) int      g_scan[N_NODES];
__device__ __align__(16) int      g_off[N_NODES];
__device__ __align__(16) int      g_bsum[NB];
__device__ __align__(16) int      g_boff[NB];
__device__ __align__(16) int      g_adj[ET];            // CSR: src per incoming slot
__device__ __align__(16) float    g_h2[N_NODES*2];
__device__ __align__(16) float    g_as2[N_NODES];
__device__ __align__(16) float    g_ad2[N_NODES];
__device__ int g_fmt64;   // 1 if edge_index buffer is int64, 0 if int32

__device__ __forceinline__ float lrelu(float x) { return x > 0.f ? x : NEG * x; }

// -------- detect int64 vs int32 edge_index layout --------
__global__ void k_detect(const int* __restrict__ ei32) {
    __shared__ int nz;
    if (threadIdx.x == 0) nz = 0;
    __syncthreads();
    int c = 0;
    for (int i = threadIdx.x; i < 1024; i += blockDim.x)
        if (ei32[2*i + 1] != 0) c++;
    atomicAdd(&nz, c);
    __syncthreads();
    if (threadIdx.x == 0) g_fmt64 = (nz == 0) ? 1 : 0;
}

// -------- init: convert edges to int32, zero degree counters --------
__global__ void k_init(const void* __restrict__ ei) {
    int i = blockIdx.x * blockDim.x + threadIdx.x;
    if (i < N_EDGES) {
        if (g_fmt64) {
            const long long* e = (const long long*)ei;
            g_src[i] = (int)e[i];
            g_dst[i] = (int)e[N_EDGES + i];
        } else {
            const int* e = (const int*)ei;
            g_src[i] = e[i];
            g_dst[i] = e[N_EDGES + i];
        }
    }
    if (i < N_NODES) { g_deg[i] = 0; g_cur[i] = 0; }
}

// -------- CSR build: count, scan (3 stages), fill --------
__global__ void k_count() {
    int i = blockIdx.x * blockDim.x + threadIdx.x;
    if (i >= ET) return;
    int d = (i < N_EDGES) ? g_dst[i] : (i - N_EDGES);
    atomicAdd(&g_deg[d], 1);
}

__global__ void k_scan1() {
    __shared__ int s[SCAN_BLK];
    int t = threadIdx.x;
    int i = blockIdx.x * SCAN_BLK + t;
    int v = (i < N_NODES) ? g_deg[i] : 0;
    s[t] = v;
    __syncthreads();
    for (int off = 1; off < SCAN_BLK; off <<= 1) {
        int x = (t >= off) ? s[t - off] : 0;
        __syncthreads();
        s[t] += x;
        __syncthreads();
    }
    if (i < N_NODES) g_scan[i] = s[t] - v;       // exclusive within block
    if (t == SCAN_BLK - 1) g_bsum[blockIdx.x] = s[t];
}

__global__ void k_scan2() {
    __shared__ int s[128];
    int t = threadIdx.x;
    int v = (t < NB) ? g_bsum[t] : 0;
    s[t] = v;
    __syncthreads();
    for (int off = 1; off < 128; off <<= 1) {
        int x = (t >= off) ? s[t - off] : 0;
        __syncthreads();
        s[t] += x;
        __syncthreads();
    }
    if (t < NB) g_boff[t] = s[t] - v;            // exclusive block offsets
}

__global__ void k_scan3() {
    int i = blockIdx.x * blockDim.x + threadIdx.x;
    if (i < N_NODES) g_off[i] = g_scan[i] + g_boff[i / SCAN_BLK];
}

__global__ void k_fill() {
    int i = blockIdx.x * blockDim.x + threadIdx.x;
    if (i >= ET) return;
    int s, d;
    if (i < N_EDGES) { s = g_src[i]; d = g_dst[i]; }
    else             { s = d = i - N_EDGES; }
    int pos = atomicAdd(&g_cur[d], 1);
    g_adj[g_off[d] + pos] = s;
}

// -------- SGEMM: C[M,256] = A[M,128] @ B[128,256] + fused attention dots ----
#define BM 64
#define BN 64
#define BK 16
__global__ void k_sgemm(const float* __restrict__ A, const float* __restrict__ B, int M,
                        const float* __restrict__ attS, const float* __restrict__ attD) {
    __shared__ float As[BK][BM];
    __shared__ float Bs[BK][BN];
    const int t  = threadIdx.x;          // 256 threads
    const int ty = t >> 4;               // 0..15
    const int tx = t & 15;               // 0..15
    const int bm = blockIdx.x * BM;
    const int bn = blockIdx.y * BN;      // = head * 64

    float acc[4][4];
#pragma unroll
    for (int i = 0; i < 4; i++)
#pragma unroll
        for (int j = 0; j < 4; j++) acc[i][j] = 0.f;

    for (int kt = 0; kt < F_IN; kt += BK) {
        {
            int row = t >> 2;            // 0..63
            int kv  = t & 3;             // 0..3 (float4 along k)
            float4 a4 = make_float4(0.f, 0.f, 0.f, 0.f);
            int ar = bm + row;
            if (ar < M) a4 = *(const float4*)(A + (size_t)ar * F_IN + kt + kv * 4);
            As[kv*4+0][row] = a4.x;
            As[kv*4+1][row] = a4.y;
            As[kv*4+2][row] = a4.z;
            As[kv*4+3][row] = a4.w;
        }
        {
            int kr = t >> 4;             // 0..15
            int cv = t & 15;             // 0..15
            float4 b4 = *(const float4*)(B + (size_t)(kt + kr) * HH + bn + cv * 4);
            *(float4*)&Bs[kr][cv*4] = b4;
        }
        __syncthreads();
#pragma unroll
        for (int k = 0; k < BK; k++) {
            float a0 = As[k][ty*4+0], a1 = As[k][ty*4+1];
            float a2 = As[k][ty*4+2], a3 = As[k][ty*4+3];
            float b0 = Bs[k][tx*4+0], b1 = Bs[k][tx*4+1];
            float b2 = Bs[k][tx*4+2], b3 = Bs[k][tx*4+3];
            acc[0][0] += a0*b0; acc[0][1] += a0*b1; acc[0][2] += a0*b2; acc[0][3] += a0*b3;
            acc[1][0] += a1*b0; acc[1][1] += a1*b1; acc[1][2] += a1*b2; acc[1][3] += a1*b3;
            acc[2][0] += a2*b0; acc[2][1] += a2*b1; acc[2][2] += a2*b2; acc[2][3] += a2*b3;
            acc[3][0] += a3*b0; acc[3][1] += a3*b1; acc[3][2] += a3*b2; acc[3][3] += a3*b3;
        }
        __syncthreads();
    }
#pragma unroll
    for (int i = 0; i < 4; i++) {
        int row = bm + ty*4 + i;
        if (row < M) {
#pragma unroll
            for (int j = 0; j < 4; j++)
                g_h1[(size_t)row * HH + bn + tx*4 + j] = acc[i][j];
        }
    }
    // fused attention dots: this block owns all 64 channels of head bn/64
    float sS[4], sD[4];
#pragma unroll
    for (int j = 0; j < 4; j++) {
        sS[j] = attS[bn + tx*4 + j];
        sD[j] = attD[bn + tx*4 + j];
    }
    float pS[4], pD[4];
#pragma unroll
    for (int i = 0; i < 4; i++) {
        pS[i] = acc[i][0]*sS[0] + acc[i][1]*sS[1] + acc[i][2]*sS[2] + acc[i][3]*sS[3];
        pD[i] = acc[i][0]*sD[0] + acc[i][1]*sD[1] + acc[i][2]*sD[2] + acc[i][3]*sD[3];
    }
#pragma unroll
    for (int o = 8; o >= 1; o >>= 1) {
#pragma unroll
        for (int i = 0; i < 4; i++) {
            pS[i] += __shfl_xor_sync(0xffffffffu, pS[i], o);
            pD[i] += __shfl_xor_sync(0xffffffffu, pD[i], o);
        }
    }
    if (tx == 0) {
        int head = bn >> 6;
#pragma unroll
        for (int i = 0; i < 4; i++) {
            int row = bm + ty*4 + i;
            if (row < M) {
                g_as1[row*4 + head] = pS[i];
                g_ad1[row*4 + head] = pD[i];
            }
        }
    }
}

// -------- fused layer1: per-dst softmax + aggregation + ELU (warp per dst) ----
__global__ void k_fused1(const float* __restrict__ b1) {
    int w    = (blockIdx.x * blockDim.x + threadIdx.x) >> 5;
    int lane = threadIdx.x & 31;
    if (w >= N_NODES) return;
    const int beg = g_off[w];
    const int end = beg + g_deg[w];
    float4 ad = *(const float4*)(g_ad1 + w*4);

    // pass 1: segment max (deg >= 1 always: self loop)
    float4 mx = make_float4(-1e30f, -1e30f, -1e30f, -1e30f);
    for (int j = beg + lane; j < end; j += 32) {
        int s = g_adj[j];
        float4 as = *(const float4*)(g_as1 + s*4);
        mx.x = fmaxf(mx.x, lrelu(as.x + ad.x));
        mx.y = fmaxf(mx.y, lrelu(as.y + ad.y));
        mx.z = fmaxf(mx.z, lrelu(as.z + ad.z));
        mx.w = fmaxf(mx.w, lrelu(as.w + ad.w));
    }
#pragma unroll
    for (int o = 16; o >= 1; o >>= 1) {
        mx.x = fmaxf(mx.x, __shfl_xor_sync(0xffffffffu, mx.x, o));
        mx.y = fmaxf(mx.y, __shfl_xor_sync(0xffffffffu, mx.y, o));
        mx.z = fmaxf(mx.z, __shfl_xor_sync(0xffffffffu, mx.z, o));
        mx.w = fmaxf(mx.w, __shfl_xor_sync(0xffffffffu, mx.w, o));
    }

    // pass 2: exp + z + weighted feature aggregation (registers)
    float4 accA = make_float4(0.f, 0.f, 0.f, 0.f);   // channels lane*4..+3     (heads 0/1)
    float4 accB = make_float4(0.f, 0.f, 0.f, 0.f);   // channels 128+lane*4..+3 (heads 2/3)
    float4 zs   = make_float4(0.f, 0.f, 0.f, 0.f);
    for (int base = beg; base < end; base += 32) {
        int j = base + lane;
        int s = 0;
        float4 ex = make_float4(0.f, 0.f, 0.f, 0.f);
        if (j < end) {
            s = g_adj[j];
            float4 as = *(const float4*)(g_as1 + s*4);
            ex.x = __expf(lrelu(as.x + ad.x) - mx.x);
            ex.y = __expf(lrelu(as.y + ad.y) - mx.y);
            ex.z = __expf(lrelu(as.z + ad.z) - mx.z);
            ex.w = __expf(lrelu(as.w + ad.w) - mx.w);
            zs.x += ex.x; zs.y += ex.y; zs.z += ex.z; zs.w += ex.w;
        }
        int cnt = min(32, end - base);
        for (int jj = 0; jj < cnt; jj++) {
            int   ss  = __shfl_sync(0xffffffffu, s, jj);
            float e0  = __shfl_sync(0xffffffffu, ex.x, jj);
            float e1  = __shfl_sync(0xffffffffu, ex.y, jj);
            float e2  = __shfl_sync(0xffffffffu, ex.z, jj);
            float e3  = __shfl_sync(0xffffffffu, ex.w, jj);
            const float4* hv = (const float4*)(g_h1 + (size_t)ss * HH);
            float4 v0 = hv[lane];
            float4 v1 = hv[32 + lane];
            float m0 = (lane < 16) ? e0 : e1;
            float m1 = (lane < 16) ? e2 : e3;
            accA.x += m0*v0.x; accA.y += m0*v0.y; accA.z += m0*v0.z; accA.w += m0*v0.w;
            accB.x += m1*v1.x; accB.y += m1*v1.y; accB.z += m1*v1.z; accB.w += m1*v1.w;
        }
    }
#pragma unroll
    for (int o = 16; o >= 1; o >>= 1) {
        zs.x += __shfl_xor_sync(0xffffffffu, zs.x, o);
        zs.y += __shfl_xor_sync(0xffffffffu, zs.y, o);
        zs.z += __shfl_xor_sync(0xffffffffu, zs.z, o);
        zs.w += __shfl_xor_sync(0xffffffffu, zs.w, o);
    }
    float zA = (lane < 16) ? zs.x : zs.y;
    float zB = (lane < 16) ? zs.z : zs.w;
    // normalize + bias + ELU, write activated output
    int c0 = lane*4, c1 = 128 + lane*4;
    const float4 bA = *(const float4*)(b1 + c0);
    const float4 bB = *(const float4*)(b1 + c1);
    float4 oA, oB;
    oA.x = accA.x/zA + bA.x; oA.y = accA.y/zA + bA.y;
    oA.z = accA.z/zA + bA.z; oA.w = accA.w/zA + bA.w;
    oB.x = accB.x/zB + bB.x; oB.y = accB.y/zB + bB.y;
    oB.z = accB.z/zB + bB.z; oB.w = accB.w/zB + bB.w;
    oA.x = oA.x > 0.f ? oA.x : (__expf(oA.x) - 1.f);
    oA.y = oA.y > 0.f ? oA.y : (__expf(oA.y) - 1.f);
    oA.z = oA.z > 0.f ? oA.z : (__expf(oA.z) - 1.f);
    oA.w = oA.w > 0.f ? oA.w : (__expf(oA.w) - 1.f);
    oB.x = oB.x > 0.f ? oB.x : (__expf(oB.x) - 1.f);
    oB.y = oB.y > 0.f ? oB.y : (__expf(oB.y) - 1.f);
    oB.z = oB.z > 0.f ? oB.z : (__expf(oB.z) - 1.f);
    oB.w = oB.w > 0.f ? oB.w : (__expf(oB.w) - 1.f);
    float4* outp = (float4*)(g_hact + (size_t)w * HH);
    outp[lane]      = oA;
    outp[32 + lane] = oB;
}

// -------- layer2 features: h2 = hact @ W2 (256->2), plus attention dots ------
__global__ void k_gemv2(const float* __restrict__ W2,
                        const float* __restrict__ attS2, const float* __restrict__ attD2) {
    int w    = (blockIdx.x * blockDim.x + threadIdx.x) >> 5;
    int lane = threadIdx.x & 31;
    if (w >= N_NODES) return;
    const float4* hv = (const float4*)(g_hact + (size_t)w * HH);
    float4 v0 = hv[lane];
    float4 v1 = hv[32 + lane];
    const float2* Wv = (const float2*)W2;     // [256] float2
    float s0 = 0.f, s1 = 0.f;
    int c0 = lane * 4;
    float2 w0;
    w0 = Wv[c0+0];      s0 += v0.x*w0.x; s1 += v0.x*w0.y;
    w0 = Wv[c0+1];      s0 += v0.y*w0.x; s1 += v0.y*w0.y;
    w0 = Wv[c0+2];      s0 += v0.z*w0.x; s1 += v0.z*w0.y;
    w0 = Wv[c0+3];      s0 += v0.w*w0.x; s1 += v0.w*w0.y;
    w0 = Wv[128+c0+0];  s0 += v1.x*w0.x; s1 += v1.x*w0.y;
    w0 = Wv[128+c0+1];  s0 += v1.y*w0.x; s1 += v1.y*w0.y;
    w0 = Wv[128+c0+2];  s0 += v1.z*w0.x; s1 += v1.z*w0.y;
    w0 = Wv[128+c0+3];  s0 += v1.w*w0.x; s1 += v1.w*w0.y;
#pragma unroll
    for (int o = 1; o < 32; o <<= 1) {
        s0 += __shfl_xor_sync(0xffffffffu, s0, o);
        s1 += __shfl_xor_sync(0xffffffffu, s1, o);
    }
    if (lane == 0) {
        g_h2[w*2]   = s0;
        g_h2[w*2+1] = s1;
        g_as2[w] = s0*attS2[0] + s1*attS2[1];
        g_ad2[w] = s0*attD2[0] + s1*attD2[1];
    }
}

// -------- fused layer2: per-dst softmax + aggregation + output (thread/dst) ----
__global__ void k_fused2(float* __restrict__ out, const float* __restrict__ b2) {
    int t = blockIdx.x * blockDim.x + threadIdx.x;
    if (t >= N_NODES) return;
    const int beg = g_off[t];
    const int end = beg + g_deg[t];
    const float ad = g_ad2[t];
    float m = -1e30f;
    for (int j = beg; j < end; j++) {
        int s = g_adj[j];
        m = fmaxf(m, lrelu(g_as2[s] + ad));
    }
    float z = 0.f, a0 = 0.f, a1 = 0.f;
    for (int j = beg; j < end; j++) {
        int s = g_adj[j];
        float ex = __expf(lrelu(g_as2[s] + ad) - m);
        z  += ex;
        a0 += ex * g_h2[2*s];
        a1 += ex * g_h2[2*s+1];
    }
    out[2*t]   = a0 / z + b2[0];
    out[2*t+1] = a1 / z + b2[1];
}

extern "C" void kernel_launch(void* const* d_in, const int* in_sizes, int n_in,
                              void* d_out, int out_size) {
    const float* x    = (const float*)d_in[0];
    const void*  ei   = d_in[1];
    const float* W1   = (const float*)d_in[2];
    const float* aS1  = (const float*)d_in[3];
    const float* aD1  = (const float*)d_in[4];
    const float* b1   = (const float*)d_in[5];
    const float* W2   = (const float*)d_in[6];
    const float* aS2  = (const float*)d_in[7];
    const float* aD2  = (const float*)d_in[8];
    const float* b2   = (const float*)d_in[9];
    float* out = (float*)d_out;

    const int TB = 256;
    k_detect<<<1, 256>>>((const int*)ei);
    k_init<<<(N_EDGES + TB - 1) / TB, TB>>>(ei);
    k_count<<<(ET + TB - 1) / TB, TB>>>();
    k_scan1<<<NB, SCAN_BLK>>>();
    k_scan2<<<1, 128>>>();
    k_scan3<<<(N_NODES + TB - 1) / TB, TB>>>();
    k_fill<<<(ET + TB - 1) / TB, TB>>>();

    dim3 gg((N_NODES + BM - 1) / BM, HH / BN);
    k_sgemm<<<gg, 256>>>(x, W1, N_NODES, aS1, aD1);

    k_fused1<<<(N_NODES*32 + TB - 1) / TB, TB>>>(b1);

    k_gemv2<<<(N_NODES*32 + TB - 1) / TB, TB>>>(W2, aS2, aD2);
    k_fused2<<<(N_NODES + TB - 1) / TB, TB>>>(out, b2);
}

// round 5
// speedup vs baseline: 1.7849x; 1.0920x over previous
#include <cuda_runtime.h>
#include <cuda_fp16.h>

#define N_NODES 50000
#define N_EDGES 800000
#define ET (N_EDGES + N_NODES)   // edges + self loops
#define F_IN 128
#define HEADS 4
#define HID 64
#define HH (HEADS*HID)           // 256
#define NEG 0.2f

#define SCAN_BLK 512
#define NB ((N_NODES + SCAN_BLK - 1) / SCAN_BLK)   // 98

// -------- device scratch (static: no allocation allowed) --------
__device__ __align__(16) __half2   g_h1h[N_NODES*128];    // layer1 features (fp16, 2ch/half2)
__device__ __align__(16) __half2   g_hacth[N_NODES*128];  // layer1 activated (fp16)
__device__ __align__(16) float     g_as1[N_NODES*HEADS];
__device__ __align__(16) float     g_ad1[N_NODES*HEADS];
__device__ __align__(16) int       g_src[N_EDGES];
__device__ __align__(16) int       g_dst[N_EDGES];
__device__ __align__(16) int       g_deg[N_NODES];
__device__ __align__(16) int       g_cur[N_NODES];
__device__ __align__(16) int       g_scan[N_NODES];
__device__ __align__(16) int       g_off[N_NODES];
__device__ __align__(16) int       g_bsum[NB];
__device__ __align__(16) int       g_boff[NB];
__device__ __align__(16) int       g_adj[ET];             // CSR: src per incoming slot
__device__ __align__(16) float     g_h2[N_NODES*2];
__device__ __align__(16) float     g_as2[N_NODES];
__device__ __align__(16) float     g_ad2[N_NODES];
__device__ int g_fmt64;

__device__ __forceinline__ float lrelu(float x) { return x > 0.f ? x : NEG * x; }

#define PACK2(d, lo, hi) asm("mov.b64 %0, {%1, %2};" : "=l"(d) : "f"(lo), "f"(hi))
#define UNPACK2(lo, hi, s) asm("mov.b64 {%0, %1}, %2;" : "=f"(lo), "=f"(hi) : "l"(s))
#define FMA2(acc, a, b) asm("fma.rn.f32x2 %0, %1, %2, %0;" : "+l"(acc) : "l"(a), "l"(b))

// -------- detect int64 vs int32 edge_index layout --------
__global__ void k_detect(const int* __restrict__ ei32) {
    __shared__ int nz;
    if (threadIdx.x == 0) nz = 0;
    __syncthreads();
    int c = 0;
    for (int i = threadIdx.x; i < 1024; i += blockDim.x)
        if (ei32[2*i + 1] != 0) c++;
    atomicAdd(&nz, c);
    __syncthreads();
    if (threadIdx.x == 0) g_fmt64 = (nz == 0) ? 1 : 0;
}

__global__ void k_init(const void* __restrict__ ei) {
    int i = blockIdx.x * blockDim.x + threadIdx.x;
    if (i < N_EDGES) {
        if (g_fmt64) {
            const long long* e = (const long long*)ei;
            g_src[i] = (int)e[i];
            g_dst[i] = (int)e[N_EDGES + i];
        } else {
            const int* e = (const int*)ei;
            g_src[i] = e[i];
            g_dst[i] = e[N_EDGES + i];
        }
    }
    if (i < N_NODES) { g_deg[i] = 0; g_cur[i] = 0; }
}

// -------- CSR build --------
__global__ void k_count() {
    int i = blockIdx.x * blockDim.x + threadIdx.x;
    if (i >= ET) return;
    int d = (i < N_EDGES) ? g_dst[i] : (i - N_EDGES);
    atomicAdd(&g_deg[d], 1);
}

__global__ void k_scan1() {
    __shared__ int s[SCAN_BLK];
    int t = threadIdx.x;
    int i = blockIdx.x * SCAN_BLK + t;
    int v = (i < N_NODES) ? g_deg[i] : 0;
    s[t] = v;
    __syncthreads();
    for (int off = 1; off < SCAN_BLK; off <<= 1) {
        int x = (t >= off) ? s[t - off] : 0;
        __syncthreads();
        s[t] += x;
        __syncthreads();
    }
    if (i < N_NODES) g_scan[i] = s[t] - v;
    if (t == SCAN_BLK - 1) g_bsum[blockIdx.x] = s[t];
}

__global__ void k_scan2() {
    __shared__ int s[128];
    int t = threadIdx.x;
    int v = (t < NB) ? g_bsum[t] : 0;
    s[t] = v;
    __syncthreads();
    for (int off = 1; off < 128; off <<= 1) {
        int x = (t >= off) ? s[t - off] : 0;
        __syncthreads();
        s[t] += x;
        __syncthreads();
    }
    if (t < NB) g_boff[t] = s[t] - v;
}

__global__ void k_scan3() {
    int i = blockIdx.x * blockDim.x + threadIdx.x;
    if (i < N_NODES) g_off[i] = g_scan[i] + g_boff[i / SCAN_BLK];
}

__global__ void k_fill() {
    int i = blockIdx.x * blockDim.x + threadIdx.x;
    if (i >= ET) return;
    int s, d;
    if (i < N_EDGES) { s = g_src[i]; d = g_dst[i]; }
    else             { s = d = i - N_EDGES; }
    int pos = atomicAdd(&g_cur[d], 1);
    g_adj[g_off[d] + pos] = s;
}

// -------- SGEMM 128x128 tile, 8x8/thread, f32x2 packed FMA, fused epilogue ----
#define BM2 128
#define BN2 128
#define BK2 16
__global__ void __launch_bounds__(256, 2)
k_sgemm(const float* __restrict__ A, const float* __restrict__ B,
        const float* __restrict__ attS, const float* __restrict__ attD) {
    __shared__ unsigned long long As2[BK2][BM2];   // (a,a) duplicated pairs
    __shared__ float4 Bs4[BK2][BN2/4];
    const int t  = threadIdx.x;          // 256
    const int tx = t & 15;
    const int ty = t >> 4;
    const int bm = blockIdx.x * BM2;
    const int bn = blockIdx.y * BN2;

    unsigned long long acc[8][4];
#pragma unroll
    for (int i = 0; i < 8; i++)
#pragma unroll
        for (int j = 0; j < 4; j++) acc[i][j] = 0ull;

    for (int kt = 0; kt < F_IN; kt += BK2) {
#pragma unroll
        for (int u = 0; u < 2; u++) {
            int idx = t*2 + u;           // 0..511 over row(128) x kv(4)
            int row = idx >> 2;
            int kv  = idx & 3;
            float4 a4 = make_float4(0.f, 0.f, 0.f, 0.f);
            int ar = bm + row;
            if (ar < N_NODES) a4 = *(const float4*)(A + (size_t)ar*F_IN + kt + kv*4);
            unsigned long long p;
            PACK2(p, a4.x, a4.x); As2[kv*4+0][row] = p;
            PACK2(p, a4.y, a4.y); As2[kv*4+1][row] = p;
            PACK2(p, a4.z, a4.z); As2[kv*4+2][row] = p;
            PACK2(p, a4.w, a4.w); As2[kv*4+3][row] = p;
        }
        {
            int kr = t >> 4;
            int cc = t & 15;
            Bs4[kr][cc]    = *(const float4*)(B + (size_t)(kt+kr)*HH + bn + cc*4);
            Bs4[kr][16+cc] = *(const float4*)(B + (size_t)(kt+kr)*HH + bn + 64 + cc*4);
        }
        __syncthreads();
#pragma unroll
        for (int k = 0; k < BK2; k++) {
            ulonglong2 aA0 = *(ulonglong2*)&As2[k][ty*4];
            ulonglong2 aA1 = *(ulonglong2*)&As2[k][ty*4+2];
            ulonglong2 aB0 = *(ulonglong2*)&As2[k][64+ty*4];
            ulonglong2 aB1 = *(ulonglong2*)&As2[k][64+ty*4+2];
            float4 b0 = Bs4[k][tx];
            float4 b1 = Bs4[k][16+tx];
            unsigned long long bp0, bp1, bp2, bp3;
            PACK2(bp0, b0.x, b0.y); PACK2(bp1, b0.z, b0.w);
            PACK2(bp2, b1.x, b1.y); PACK2(bp3, b1.z, b1.w);
            unsigned long long av[8] = {aA0.x, aA0.y, aA1.x, aA1.y,
                                        aB0.x, aB0.y, aB1.x, aB1.y};
#pragma unroll
            for (int r = 0; r < 8; r++) {
                FMA2(acc[r][0], av[r], bp0);
                FMA2(acc[r][1], av[r], bp1);
                FMA2(acc[r][2], av[r], bp2);
                FMA2(acc[r][3], av[r], bp3);
            }
        }
        __syncthreads();
    }

    // epilogue: store fp16 h1 + fused attention dots (fp32)
    const int h0 = bn >> 6;              // first head of this col tile
    float sSA[4], sSB[4], sDA[4], sDB[4];
#pragma unroll
    for (int j = 0; j < 4; j++) {
        int cA = bn + tx*4 + j;
        int cB = cA + 64;
        sSA[j] = attS[cA]; sDA[j] = attD[cA];
        sSB[j] = attS[cB]; sDB[j] = attD[cB];
    }
#pragma unroll
    for (int r = 0; r < 8; r++) {
        int row = bm + ((r < 4) ? (ty*4 + r) : (64 + ty*4 + r - 4));
        float f0,f1,f2,f3,f4,f5,f6,f7;
        UNPACK2(f0, f1, acc[r][0]);
        UNPACK2(f2, f3, acc[r][1]);
        UNPACK2(f4, f5, acc[r][2]);
        UNPACK2(f6, f7, acc[r][3]);
        if (row < N_NODES) {
            __half2 hA0 = __floats2half2_rn(f0, f1);
            __half2 hA1 = __floats2half2_rn(f2, f3);
            __half2 hB0 = __floats2half2_rn(f4, f5);
            __half2 hB1 = __floats2half2_rn(f6, f7);
            __half2* rp = g_h1h + (size_t)row*128 + (bn >> 1);
            uint2 vA; vA.x = *(unsigned*)&hA0; vA.y = *(unsigned*)&hA1;
            uint2 vB; vB.x = *(unsigned*)&hB0; vB.y = *(unsigned*)&hB1;
            *(uint2*)(rp + tx*2)      = vA;
            *(uint2*)(rp + 32 + tx*2) = vB;
        }
        float pSA = f0*sSA[0] + f1*sSA[1] + f2*sSA[2] + f3*sSA[3];
        float pDA = f0*sDA[0] + f1*sDA[1] + f2*sDA[2] + f3*sDA[3];
        float pSB = f4*sSB[0] + f5*sSB[1] + f6*sSB[2] + f7*sSB[3];
        float pDB = f4*sDB[0] + f5*sDB[1] + f6*sDB[2] + f7*sDB[3];
#pragma unroll
        for (int o = 8; o >= 1; o >>= 1) {
            pSA += __shfl_xor_sync(0xffffffffu, pSA, o);
            pDA += __shfl_xor_sync(0xffffffffu, pDA, o);
            pSB += __shfl_xor_sync(0xffffffffu, pSB, o);
            pDB += __shfl_xor_sync(0xffffffffu, pDB, o);
        }
        if (tx == 0 && row < N_NODES) {
            g_as1[row*4 + h0]     = pSA;
            g_as1[row*4 + h0 + 1] = pSB;
            g_ad1[row*4 + h0]     = pDA;
            g_ad1[row*4 + h0 + 1] = pDB;
        }
    }
}

// -------- fused layer1: softmax + aggregation + ELU (warp per dst, fp16 feats) --
__global__ void k_fused1(const float* __restrict__ b1) {
    int w    = (blockIdx.x * blockDim.x + threadIdx.x) >> 5;
    int lane = threadIdx.x & 31;
    if (w >= N_NODES) return;
    const int beg = g_off[w];
    const int end = beg + g_deg[w];
    float4 ad = *(const float4*)(g_ad1 + w*4);

    // pass 1: segment max
    float4 mx = make_float4(-1e30f, -1e30f, -1e30f, -1e30f);
    for (int j = beg + lane; j < end; j += 32) {
        int s = g_adj[j];
        float4 as = *(const float4*)(g_as1 + s*4);
        mx.x = fmaxf(mx.x, lrelu(as.x + ad.x));
        mx.y = fmaxf(mx.y, lrelu(as.y + ad.y));
        mx.z = fmaxf(mx.z, lrelu(as.z + ad.z));
        mx.w = fmaxf(mx.w, lrelu(as.w + ad.w));
    }
#pragma unroll
    for (int o = 16; o >= 1; o >>= 1) {
        mx.x = fmaxf(mx.x, __shfl_xor_sync(0xffffffffu, mx.x, o));
        mx.y = fmaxf(mx.y, __shfl_xor_sync(0xffffffffu, mx.y, o));
        mx.z = fmaxf(mx.z, __shfl_xor_sync(0xffffffffu, mx.z, o));
        mx.w = fmaxf(mx.w, __shfl_xor_sync(0xffffffffu, mx.w, o));
    }

    // pass 2: exp + z + weighted aggregation; lane owns channels [lane*8, lane*8+7]
    const int hd = lane >> 3;            // head of this lane's channels
    float acc0=0.f,acc1=0.f,acc2=0.f,acc3=0.f,acc4=0.f,acc5=0.f,acc6=0.f,acc7=0.f;
    float4 zs = make_float4(0.f, 0.f, 0.f, 0.f);
    for (int base = beg; base < end; base += 32) {
        int j = base + lane;
        int s = 0;
        float4 ex = make_float4(0.f, 0.f, 0.f, 0.f);
        if (j < end) {
            s = g_adj[j];
            float4 as = *(const float4*)(g_as1 + s*4);
            ex.x = __expf(lrelu(as.x + ad.x) - mx.x);
            ex.y = __expf(lrelu(as.y + ad.y) - mx.y);
            ex.z = __expf(lrelu(as.z + ad.z) - mx.z);
            ex.w = __expf(lrelu(as.w + ad.w) - mx.w);
            zs.x += ex.x; zs.y += ex.y; zs.z += ex.z; zs.w += ex.w;
        }
        int cnt = min(32, end - base);
        for (int jj = 0; jj < cnt; jj++) {
            int   ss = __shfl_sync(0xffffffffu, s, jj);
            float e0 = __shfl_sync(0xffffffffu, ex.x, jj);
            float e1 = __shfl_sync(0xffffffffu, ex.y, jj);
            float e2 = __shfl_sync(0xffffffffu, ex.z, jj);
            float e3 = __shfl_sync(0xffffffffu, ex.w, jj);
            float eh = (hd == 0) ? e0 : (hd == 1) ? e1 : (hd == 2) ? e2 : e3;
            float4 hv = *((const float4*)g_h1h + (size_t)ss*32 + lane);
            const __half2* ph = (const __half2*)&hv;
            float2 q0 = __half22float2(ph[0]);
            float2 q1 = __half22float2(ph[1]);
            float2 q2 = __half22float2(ph[2]);
            float2 q3 = __half22float2(ph[3]);
            acc0 += eh*q0.x; acc1 += eh*q0.y;
            acc2 += eh*q1.x; acc3 += eh*q1.y;
            acc4 += eh*q2.x; acc5 += eh*q2.y;
            acc6 += eh*q3.x; acc7 += eh*q3.y;
        }
    }
#pragma unroll
    for (int o = 16; o >= 1; o >>= 1) {
        zs.x += __shfl_xor_sync(0xffffffffu, zs.x, o);
        zs.y += __shfl_xor_sync(0xffffffffu, zs.y, o);
        zs.z += __shfl_xor_sync(0xffffffffu, zs.z, o);
        zs.w += __shfl_xor_sync(0xffffffffu, zs.w, o);
    }
    float zh = (hd == 0) ? zs.x : (hd == 1) ? zs.y : (hd == 2) ? zs.z : zs.w;
    float4 bA = *(const float4*)(b1 + lane*8);
    float4 bB = *(const float4*)(b1 + lane*8 + 4);
    float o0 = acc0/zh + bA.x, o1 = acc1/zh + bA.y;
    float o2 = acc2/zh + bA.z, o3 = acc3/zh + bA.w;
    float o4 = acc4/zh + bB.x, o5 = acc5/zh + bB.y;
    float o6 = acc6/zh + bB.z, o7 = acc7/zh + bB.w;
    o0 = o0 > 0.f ? o0 : (__expf(o0) - 1.f);
    o1 = o1 > 0.f ? o1 : (__expf(o1) - 1.f);
    o2 = o2 > 0.f ? o2 : (__expf(o2) - 1.f);
    o3 = o3 > 0.f ? o3 : (__expf(o3) - 1.f);
    o4 = o4 > 0.f ? o4 : (__expf(o4) - 1.f);
    o5 = o5 > 0.f ? o5 : (__expf(o5) - 1.f);
    o6 = o6 > 0.f ? o6 : (__expf(o6) - 1.f);
    o7 = o7 > 0.f ? o7 : (__expf(o7) - 1.f);
    __half2 p0 = __floats2half2_rn(o0, o1);
    __half2 p1 = __floats2half2_rn(o2, o3);
    __half2 p2 = __floats2half2_rn(o4, o5);
    __half2 p3 = __floats2half2_rn(o6, o7);
    uint4 st;
    st.x = *(unsigned*)&p0; st.y = *(unsigned*)&p1;
    st.z = *(unsigned*)&p2; st.w = *(unsigned*)&p3;
    ((uint4*)(g_hacth + (size_t)w*128))[lane] = st;
}

// -------- layer2: h2 = hact @ W2 (256->2) + attention dots (warp per node) ----
__global__ void k_gemv2(const float* __restrict__ W2,
                        const float* __restrict__ attS2, const float* __restrict__ attD2) {
    int w    = (blockIdx.x * blockDim.x + threadIdx.x) >> 5;
    int lane = threadIdx.x & 31;
    if (w >= N_NODES) return;
    float4 hv = *((const float4*)g_hacth + (size_t)w*32 + lane);
    const __half2* ph = (const __half2*)&hv;
    float2 q0 = __half22float2(ph[0]);
    float2 q1 = __half22float2(ph[1]);
    float2 q2 = __half22float2(ph[2]);
    float2 q3 = __half22float2(ph[3]);
    // W2 row-major [256][2]; lane channels lane*8..+7 -> floats W2[lane*16 .. +15]
    const float4* Wv = (const float4*)(W2 + lane*16);
    float4 w0 = Wv[0], w1 = Wv[1], w2 = Wv[2], w3 = Wv[3];
    float s0 = q0.x*w0.x + q0.y*w0.z + q1.x*w1.x + q1.y*w1.z
             + q2.x*w2.x + q2.y*w2.z + q3.x*w3.x + q3.y*w3.z;
    float s1 = q0.x*w0.y + q0.y*w0.w + q1.x*w1.y + q1.y*w1.w
             + q2.x*w2.y + q2.y*w2.w + q3.x*w3.y + q3.y*w3.w;
#pragma unroll
    for (int o = 16; o >= 1; o >>= 1) {
        s0 += __shfl_xor_sync(0xffffffffu, s0, o);
        s1 += __shfl_xor_sync(0xffffffffu, s1, o);
    }
    if (lane == 0) {
        g_h2[w*2]   = s0;
        g_h2[w*2+1] = s1;
        g_as2[w] = s0*attS2[0] + s1*attS2[1];
        g_ad2[w] = s0*attD2[0] + s1*attD2[1];
    }
}

// -------- fused layer2 (thread per dst) --------
__global__ void k_fused2(float* __restrict__ out, const float* __restrict__ b2) {
    int t = blockIdx.x * blockDim.x + threadIdx.x;
    if (t >= N_NODES) return;
    const int beg = g_off[t];
    const int end = beg + g_deg[t];
    const float ad = g_ad2[t];
    float m = -1e30f;
    for (int j = beg; j < end; j++) {
        int s = g_adj[j];
        m = fmaxf(m, lrelu(g_as2[s] + ad));
    }
    float z = 0.f, a0 = 0.f, a1 = 0.f;
    for (int j = beg; j < end; j++) {
        int s = g_adj[j];
        float ex = __expf(lrelu(g_as2[s] + ad) - m);
        z  += ex;
        a0 += ex * g_h2[2*s];
        a1 += ex * g_h2[2*s+1];
    }
    out[2*t]   = a0 / z + b2[0];
    out[2*t+1] = a1 / z + b2[1];
}

extern "C" void kernel_launch(void* const* d_in, const int* in_sizes, int n_in,
                              void* d_out, int out_size) {
    const float* x    = (const float*)d_in[0];
    const void*  ei   = d_in[1];
    const float* W1   = (const float*)d_in[2];
    const float* aS1  = (const float*)d_in[3];
    const float* aD1  = (const float*)d_in[4];
    const float* b1   = (const float*)d_in[5];
    const float* W2   = (const float*)d_in[6];
    const float* aS2  = (const float*)d_in[7];
    const float* aD2  = (const float*)d_in[8];
    const float* b2   = (const float*)d_in[9];
    float* out = (float*)d_out;

    const int TB = 256;
    k_detect<<<1, 256>>>((const int*)ei);
    k_init<<<(N_EDGES + TB - 1) / TB, TB>>>(ei);
    k_count<<<(ET + TB - 1) / TB, TB>>>();
    k_scan1<<<NB, SCAN_BLK>>>();
    k_scan2<<<1, 128>>>();
    k_scan3<<<(N_NODES + TB - 1) / TB, TB>>>();
    k_fill<<<(ET + TB - 1) / TB, TB>>>();

    dim3 gg((N_NODES + BM2 - 1) / BM2, HH / BN2);
    k_sgemm<<<gg, 256>>>(x, W1, aS1, aD1);

    k_fused1<<<(N_NODES*32 + TB - 1) / TB, TB>>>(b1);

    k_gemv2<<<(N_NODES*32 + TB - 1) / TB, TB>>>(W2, aS2, aD2);
    k_fused2<<<(N_NODES + TB - 1) / TB, TB>>>(out, b2);
}

// round 6
// speedup vs baseline: 1.7899x; 1.0028x over previous
#include <cuda_runtime.h>
#include <cuda_fp16.h>

#define N_NODES 50000
#define N_EDGES 800000
#define ET (N_EDGES + N_NODES)   // edges + self loops
#define F_IN 128
#define HEADS 4
#define HID 64
#define HH (HEADS*HID)           // 256
#define NEG 0.2f

#define SCAN_BLK 512
#define NB ((N_NODES + SCAN_BLK - 1) / SCAN_BLK)   // 98

// -------- device scratch (static: no allocation allowed) --------
__device__ __align__(16) __half2   g_h1h[N_NODES*128];    // layer1 features (fp16)
__device__ __align__(16) __half2   g_hacth[N_NODES*128];  // layer1 activated (fp16)
__device__ __align__(16) float     g_as1[N_NODES*HEADS];
__device__ __align__(16) float     g_ad1[N_NODES*HEADS];
__device__ __align__(16) int       g_src[N_EDGES];
__device__ __align__(16) int       g_dst[N_EDGES];
__device__ __align__(16) int       g_deg[N_NODES];
__device__ __align__(16) int       g_cur[N_NODES];
__device__ __align__(16) int       g_scan[N_NODES];
__device__ __align__(16) int       g_off[N_NODES];
__device__ __align__(16) int       g_bsum[NB];
__device__ __align__(16) int       g_boff[NB];
__device__ __align__(16) int       g_adj[ET];             // CSR: src per incoming slot
__device__ __align__(16) float     g_h2[N_NODES*2];
__device__ __align__(16) float     g_as2[N_NODES];
__device__ __align__(16) float     g_ad2[N_NODES];
__device__ int g_fmt64;

__device__ __forceinline__ float lrelu(float x) { return x > 0.f ? x : NEG * x; }

#define PACK2(d, lo, hi) asm("mov.b64 %0, {%1, %2};" : "=l"(d) : "f"(lo), "f"(hi))
#define UNPACK2(lo, hi, s) asm("mov.b64 {%0, %1}, %2;" : "=f"(lo), "=f"(hi) : "l"(s))
#define FMA2(acc, a, b) asm("fma.rn.f32x2 %0, %1, %2, %0;" : "+l"(acc) : "l"(a), "l"(b))

// -------- zero degree counters (deg=1 seeds the self loop) --------
__global__ void k_zero() {
    int i = blockIdx.x * blockDim.x + threadIdx.x;
    if (i < N_NODES) { g_deg[i] = 1; g_cur[i] = 0; }
}

// -------- detect int64 vs int32 edge_index layout --------
__global__ void k_detect(const int* __restrict__ ei32) {
    __shared__ int nz;
    if (threadIdx.x == 0) nz = 0;
    __syncthreads();
    int c = 0;
    for (int i = threadIdx.x; i < 1024; i += blockDim.x)
        if (ei32[2*i + 1] != 0) c++;
    atomicAdd(&nz, c);
    __syncthreads();
    if (threadIdx.x == 0) g_fmt64 = (nz == 0) ? 1 : 0;
}

// -------- init: convert edges to int32 AND count in-degrees --------
__global__ void k_init(const void* __restrict__ ei) {
    int i = blockIdx.x * blockDim.x + threadIdx.x;
    if (i >= N_EDGES) return;
    int s, d;
    if (g_fmt64) {
        const long long* e = (const long long*)ei;
        s = (int)e[i];
        d = (int)e[N_EDGES + i];
    } else {
        const int* e = (const int*)ei;
        s = e[i];
        d = e[N_EDGES + i];
    }
    g_src[i] = s;
    g_dst[i] = d;
    atomicAdd(&g_deg[d], 1);
}

// -------- scan (3 stages) --------
__global__ void k_scan1() {
    __shared__ int s[SCAN_BLK];
    int t = threadIdx.x;
    int i = blockIdx.x * SCAN_BLK + t;
    int v = (i < N_NODES) ? g_deg[i] : 0;
    s[t] = v;
    __syncthreads();
    for (int off = 1; off < SCAN_BLK; off <<= 1) {
        int x = (t >= off) ? s[t - off] : 0;
        __syncthreads();
        s[t] += x;
        __syncthreads();
    }
    if (i < N_NODES) g_scan[i] = s[t] - v;
    if (t == SCAN_BLK - 1) g_bsum[blockIdx.x] = s[t];
}

__global__ void k_scan2() {
    __shared__ int s[128];
    int t = threadIdx.x;
    int v = (t < NB) ? g_bsum[t] : 0;
    s[t] = v;
    __syncthreads();
    for (int off = 1; off < 128; off <<= 1) {
        int x = (t >= off) ? s[t - off] : 0;
        __syncthreads();
        s[t] += x;
        __syncthreads();
    }
    if (t < NB) g_boff[t] = s[t] - v;
}

__global__ void k_scan3() {
    int i = blockIdx.x * blockDim.x + threadIdx.x;
    if (i < N_NODES) g_off[i] = g_scan[i] + g_boff[i / SCAN_BLK];
}

__global__ void k_fill() {
    int i = blockIdx.x * blockDim.x + threadIdx.x;
    if (i >= ET) return;
    int s, d;
    if (i < N_EDGES) { s = g_src[i]; d = g_dst[i]; }
    else             { s = d = i - N_EDGES; }
    int pos = atomicAdd(&g_cur[d], 1);
    g_adj[g_off[d] + pos] = s;
}

// -------- SGEMM 128x128 tile, 8x8/thread, f32x2 packed FMA, fused epilogue ----
#define BM2 128
#define BN2 128
#define BK2 16
__global__ void __launch_bounds__(256, 2)
k_sgemm(const float* __restrict__ A, const float* __restrict__ B,
        const float* __restrict__ attS, const float* __restrict__ attD) {
    __shared__ unsigned long long As2[BK2][BM2];   // (a,a) duplicated pairs
    __shared__ float4 Bs4[BK2][BN2/4];
    const int t  = threadIdx.x;          // 256
    const int tx = t & 15;
    const int ty = t >> 4;
    const int bm = blockIdx.x * BM2;
    const int bn = blockIdx.y * BN2;

    unsigned long long acc[8][4];
#pragma unroll
    for (int i = 0; i < 8; i++)
#pragma unroll
        for (int j = 0; j < 4; j++) acc[i][j] = 0ull;

    for (int kt = 0; kt < F_IN; kt += BK2) {
#pragma unroll
        for (int u = 0; u < 2; u++) {
            int idx = t*2 + u;           // 0..511 over row(128) x kv(4)
            int row = idx >> 2;
            int kv  = idx & 3;
            float4 a4 = make_float4(0.f, 0.f, 0.f, 0.f);
            int ar = bm + row;
            if (ar < N_NODES) a4 = *(const float4*)(A + (size_t)ar*F_IN + kt + kv*4);
            unsigned long long p;
            PACK2(p, a4.x, a4.x); As2[kv*4+0][row] = p;
            PACK2(p, a4.y, a4.y); As2[kv*4+1][row] = p;
            PACK2(p, a4.z, a4.z); As2[kv*4+2][row] = p;
            PACK2(p, a4.w, a4.w); As2[kv*4+3][row] = p;
        }
        {
            int kr = t >> 4;
            int cc = t & 15;
            Bs4[kr][cc]    = *(const float4*)(B + (size_t)(kt+kr)*HH + bn + cc*4);
            Bs4[kr][16+cc] = *(const float4*)(B + (size_t)(kt+kr)*HH + bn + 64 + cc*4);
        }
        __syncthreads();
#pragma unroll
        for (int k = 0; k < BK2; k++) {
            ulonglong2 aA0 = *(ulonglong2*)&As2[k][ty*4];
            ulonglong2 aA1 = *(ulonglong2*)&As2[k][ty*4+2];
            ulonglong2 aB0 = *(ulonglong2*)&As2[k][64+ty*4];
            ulonglong2 aB1 = *(ulonglong2*)&As2[k][64+ty*4+2];
            float4 b0 = Bs4[k][tx];
            float4 b1 = Bs4[k][16+tx];
            unsigned long long bp0, bp1, bp2, bp3;
            PACK2(bp0, b0.x, b0.y); PACK2(bp1, b0.z, b0.w);
            PACK2(bp2, b1.x, b1.y); PACK2(bp3, b1.z, b1.w);
            unsigned long long av[8] = {aA0.x, aA0.y, aA1.x, aA1.y,
                                        aB0.x, aB0.y, aB1.x, aB1.y};
#pragma unroll
            for (int r = 0; r < 8; r++) {
                FMA2(acc[r][0], av[r], bp0);
                FMA2(acc[r][1], av[r], bp1);
                FMA2(acc[r][2], av[r], bp2);
                FMA2(acc[r][3], av[r], bp3);
            }
        }
        __syncthreads();
    }

    // epilogue: store fp16 h1 + fused attention dots (fp32)
    const int h0 = bn >> 6;              // first head of this col tile
    float sSA[4], sSB[4], sDA[4], sDB[4];
#pragma unroll
    for (int j = 0; j < 4; j++) {
        int cA = bn + tx*4 + j;
        int cB = cA + 64;
        sSA[j] = attS[cA]; sDA[j] = attD[cA];
        sSB[j] = attS[cB]; sDB[j] = attD[cB];
    }
#pragma unroll
    for (int r = 0; r < 8; r++) {
        int row = bm + ((r < 4) ? (ty*4 + r) : (64 + ty*4 + r - 4));
        float f0,f1,f2,f3,f4,f5,f6,f7;
        UNPACK2(f0, f1, acc[r][0]);
        UNPACK2(f2, f3, acc[r][1]);
        UNPACK2(f4, f5, acc[r][2]);
        UNPACK2(f6, f7, acc[r][3]);
        if (row < N_NODES) {
            __half2 hA0 = __floats2half2_rn(f0, f1);
            __half2 hA1 = __floats2half2_rn(f2, f3);
            __half2 hB0 = __floats2half2_rn(f4, f5);
            __half2 hB1 = __floats2half2_rn(f6, f7);
            __half2* rp = g_h1h + (size_t)row*128 + (bn >> 1);
            uint2 vA; vA.x = *(unsigned*)&hA0; vA.y = *(unsigned*)&hA1;
            uint2 vB; vB.x = *(unsigned*)&hB0; vB.y = *(unsigned*)&hB1;
            *(uint2*)(rp + tx*2)      = vA;
            *(uint2*)(rp + 32 + tx*2) = vB;
        }
        float pSA = f0*sSA[0] + f1*sSA[1] + f2*sSA[2] + f3*sSA[3];
        float pDA = f0*sDA[0] + f1*sDA[1] + f2*sDA[2] + f3*sDA[3];
        float pSB = f4*sSB[0] + f5*sSB[1] + f6*sSB[2] + f7*sSB[3];
        float pDB = f4*sDB[0] + f5*sDB[1] + f6*sDB[2] + f7*sDB[3];
#pragma unroll
        for (int o = 8; o >= 1; o >>= 1) {
            pSA += __shfl_xor_sync(0xffffffffu, pSA, o);
            pDA += __shfl_xor_sync(0xffffffffu, pDA, o);
            pSB += __shfl_xor_sync(0xffffffffu, pSB, o);
            pDB += __shfl_xor_sync(0xffffffffu, pDB, o);
        }
        if (tx == 0 && row < N_NODES) {
            g_as1[row*4 + h0]     = pSA;
            g_as1[row*4 + h0 + 1] = pSB;
            g_ad1[row*4 + h0]     = pDA;
            g_ad1[row*4 + h0 + 1] = pDB;
        }
    }
}

// -------- fused layer1: softmax (no max shift) + aggregation + ELU ----------
__global__ void k_fused1(const float* __restrict__ b1) {
    int w    = (blockIdx.x * blockDim.x + threadIdx.x) >> 5;
    int lane = threadIdx.x & 31;
    if (w >= N_NODES) return;
    const int beg = g_off[w];
    const int end = beg + g_deg[w];
    float4 ad = *(const float4*)(g_ad1 + w*4);

    // single pass: exp + z + weighted aggregation; lane owns channels [lane*8 .. +7]
    const int hd = lane >> 3;            // head of this lane's channels
    float acc0=0.f,acc1=0.f,acc2=0.f,acc3=0.f,acc4=0.f,acc5=0.f,acc6=0.f,acc7=0.f;
    float4 zs = make_float4(0.f, 0.f, 0.f, 0.f);
    for (int base = beg; base < end; base += 32) {
        int j = base + lane;
        int s = 0;
        float4 ex = make_float4(0.f, 0.f, 0.f, 0.f);
        if (j < end) {
            s = g_adj[j];
            float4 as = *(const float4*)(g_as1 + s*4);
            ex.x = __expf(lrelu(as.x + ad.x));
            ex.y = __expf(lrelu(as.y + ad.y));
            ex.z = __expf(lrelu(as.z + ad.z));
            ex.w = __expf(lrelu(as.w + ad.w));
            zs.x += ex.x; zs.y += ex.y; zs.z += ex.z; zs.w += ex.w;
        }
        int cnt = min(32, end - base);
        for (int jj = 0; jj < cnt; jj++) {
            int   ss = __shfl_sync(0xffffffffu, s, jj);
            float e0 = __shfl_sync(0xffffffffu, ex.x, jj);
            float e1 = __shfl_sync(0xffffffffu, ex.y, jj);
            float e2 = __shfl_sync(0xffffffffu, ex.z, jj);
            float e3 = __shfl_sync(0xffffffffu, ex.w, jj);
            float eh = (hd == 0) ? e0 : (hd == 1) ? e1 : (hd == 2) ? e2 : e3;
            float4 hv = *((const float4*)g_h1h + (size_t)ss*32 + lane);
            const __half2* ph = (const __half2*)&hv;
            float2 q0 = __half22float2(ph[0]);
            float2 q1 = __half22float2(ph[1]);
            float2 q2 = __half22float2(ph[2]);
            float2 q3 = __half22float2(ph[3]);
            acc0 += eh*q0.x; acc1 += eh*q0.y;
            acc2 += eh*q1.x; acc3 += eh*q1.y;
            acc4 += eh*q2.x; acc5 += eh*q2.y;
            acc6 += eh*q3.x; acc7 += eh*q3.y;
        }
    }
#pragma unroll
    for (int o = 16; o >= 1; o >>= 1) {
        zs.x += __shfl_xor_sync(0xffffffffu, zs.x, o);
        zs.y += __shfl_xor_sync(0xffffffffu, zs.y, o);
        zs.z += __shfl_xor_sync(0xffffffffu, zs.z, o);
        zs.w += __shfl_xor_sync(0xffffffffu, zs.w, o);
    }
    float zh = (hd == 0) ? zs.x : (hd == 1) ? zs.y : (hd == 2) ? zs.z : zs.w;
    float4 bA = *(const float4*)(b1 + lane*8);
    float4 bB = *(const float4*)(b1 + lane*8 + 4);
    float o0 = acc0/zh + bA.x, o1 = acc1/zh + bA.y;
    float o2 = acc2/zh + bA.z, o3 = acc3/zh + bA.w;
    float o4 = acc4/zh + bB.x, o5 = acc5/zh + bB.y;
    float o6 = acc6/zh + bB.z, o7 = acc7/zh + bB.w;
    o0 = o0 > 0.f ? o0 : (__expf(o0) - 1.f);
    o1 = o1 > 0.f ? o1 : (__expf(o1) - 1.f);
    o2 = o2 > 0.f ? o2 : (__expf(o2) - 1.f);
    o3 = o3 > 0.f ? o3 : (__expf(o3) - 1.f);
    o4 = o4 > 0.f ? o4 : (__expf(o4) - 1.f);
    o5 = o5 > 0.f ? o5 : (__expf(o5) - 1.f);
    o6 = o6 > 0.f ? o6 : (__expf(o6) - 1.f);
    o7 = o7 > 0.f ? o7 : (__expf(o7) - 1.f);
    __half2 p0 = __floats2half2_rn(o0, o1);
    __half2 p1 = __floats2half2_rn(o2, o3);
    __half2 p2 = __floats2half2_rn(o4, o5);
    __half2 p3 = __floats2half2_rn(o6, o7);
    uint4 st;
    st.x = *(unsigned*)&p0; st.y = *(unsigned*)&p1;
    st.z = *(unsigned*)&p2; st.w = *(unsigned*)&p3;
    ((uint4*)(g_hacth + (size_t)w*128))[lane] = st;
}

// -------- layer2: h2 = hact @ W2 (256->2) + attention dots (warp per node) ----
__global__ void k_gemv2(const float* __restrict__ W2,
                        const float* __restrict__ attS2, const float* __restrict__ attD2) {
    int w    = (blockIdx.x * blockDim.x + threadIdx.x) >> 5;
    int lane = threadIdx.x & 31;
    if (w >= N_NODES) return;
    float4 hv = *((const float4*)g_hacth + (size_t)w*32 + lane);
    const __half2* ph = (const __half2*)&hv;
    float2 q0 = __half22float2(ph[0]);
    float2 q1 = __half22float2(ph[1]);
    float2 q2 = __half22float2(ph[2]);
    float2 q3 = __half22float2(ph[3]);
    const float4* Wv = (const float4*)(W2 + lane*16);
    float4 w0 = Wv[0], w1 = Wv[1], w2 = Wv[2], w3 = Wv[3];
    float s0 = q0.x*w0.x + q0.y*w0.z + q1.x*w1.x + q1.y*w1.z
             + q2.x*w2.x + q2.y*w2.z + q3.x*w3.x + q3.y*w3.z;
    float s1 = q0.x*w0.y + q0.y*w0.w + q1.x*w1.y + q1.y*w1.w
             + q2.x*w2.y + q2.y*w2.w + q3.x*w3.y + q3.y*w3.w;
#pragma unroll
    for (int o = 16; o >= 1; o >>= 1) {
        s0 += __shfl_xor_sync(0xffffffffu, s0, o);
        s1 += __shfl_xor_sync(0xffffffffu, s1, o);
    }
    if (lane == 0) {
        g_h2[w*2]   = s0;
        g_h2[w*2+1] = s1;
        g_as2[w] = s0*attS2[0] + s1*attS2[1];
        g_ad2[w] = s0*attD2[0] + s1*attD2[1];
    }
}

// -------- fused layer2 (thread per dst, single pass, no max shift) ----------
__global__ void k_fused2(float* __restrict__ out, const float* __restrict__ b2) {
    int t = blockIdx.x * blockDim.x + threadIdx.x;
    if (t >= N_NODES) return;
    const int beg = g_off[t];
    const int end = beg + g_deg[t];
    const float ad = g_ad2[t];
    float z = 0.f, a0 = 0.f, a1 = 0.f;
    for (int j = beg; j < end; j++) {
        int s = g_adj[j];
        float ex = __expf(lrelu(g_as2[s] + ad));
        z  += ex;
        a0 += ex * g_h2[2*s];
        a1 += ex * g_h2[2*s+1];
    }
    out[2*t]   = a0 / z + b2[0];
    out[2*t+1] = a1 / z + b2[1];
}

extern "C" void kernel_launch(void* const* d_in, const int* in_sizes, int n_in,
                              void* d_out, int out_size) {
    const float* x    = (const float*)d_in[0];
    const void*  ei   = d_in[1];
    const float* W1   = (const float*)d_in[2];
    const float* aS1  = (const float*)d_in[3];
    const float* aD1  = (const float*)d_in[4];
    const float* b1   = (const float*)d_in[5];
    const float* W2   = (const float*)d_in[6];
    const float* aS2  = (const float*)d_in[7];
    const float* aD2  = (const float*)d_in[8];
    const float* b2   = (const float*)d_in[9];
    float* out = (float*)d_out;

    const int TB = 256;
    // launch order arranged so k_sgemm is launch index 3 (the one ncu profiles)
    k_zero<<<(N_NODES + TB - 1) / TB, TB>>>();                 // 0
    k_detect<<<1, 256>>>((const int*)ei);                      // 1
    k_init<<<(N_EDGES + TB - 1) / TB, TB>>>(ei);               // 2
    dim3 gg((N_NODES + BM2 - 1) / BM2, HH / BN2);
    k_sgemm<<<gg, 256>>>(x, W1, aS1, aD1);                     // 3  <- profiled
    k_scan1<<<NB, SCAN_BLK>>>();                               // 4
    k_scan2<<<1, 128>>>();                                     // 5
    k_scan3<<<(N_NODES + TB - 1) / TB, TB>>>();                // 6
    k_fill<<<(ET + TB - 1) / TB, TB>>>();                      // 7
    k_fused1<<<(N_NODES*32 + TB - 1) / TB, TB>>>(b1);          // 8
    k_gemv2<<<(N_NODES*32 + TB - 1) / TB, TB>>>(W2, aS2, aD2); // 9
    k_fused2<<<(N_NODES + TB - 1) / TB, TB>>>(out, b2);        // 10
}

// round 8
// speedup vs baseline: 2.7344x; 1.5277x over previous
#include <cuda_runtime.h>
#include <cuda_fp16.h>

#define N_NODES 50000
#define N_EDGES 800000
#define ET (N_EDGES + N_NODES)   // edges + self loops
#define F_IN 128
#define HEADS 4
#define HID 64
#define HH (HEADS*HID)           // 256
#define NEG 0.2f

#define SCAN_BLK 512
#define NB ((N_NODES + SCAN_BLK - 1) / SCAN_BLK)   // 98

// -------- device scratch (static: no allocation allowed) --------
__device__ __align__(16) __half    g_xh[N_NODES*F_IN];    // x in fp16
__device__ __align__(16) __half    g_w1h[F_IN*HH];        // W1 in fp16
__device__ __align__(16) __half2   g_h1h[N_NODES*128];    // layer1 features (fp16)
__device__ __align__(16) float     g_as1[N_NODES*HEADS];
__device__ __align__(16) float     g_ad1[N_NODES*HEADS];
__device__ __align__(16) int       g_src[N_EDGES];
__device__ __align__(16) int       g_dst[N_EDGES];
__device__ __align__(16) int       g_deg[N_NODES];
__device__ __align__(16) int       g_cur[N_NODES];
__device__ __align__(16) int       g_scan[N_NODES];
__device__ __align__(16) int       g_off[N_NODES];
__device__ __align__(16) int       g_bsum[NB];
__device__ __align__(16) int       g_boff[NB];
__device__ __align__(16) int       g_adj[ET];             // CSR: src per incoming slot
__device__ __align__(16) float     g_h2[N_NODES*2];
__device__ __align__(16) float     g_as2[N_NODES];
__device__ __align__(16) float     g_ad2[N_NODES];
__device__ int g_fmt64;

__device__ __forceinline__ float lrelu(float x) { return x > 0.f ? x : NEG * x; }

__device__ __forceinline__ unsigned s2u(const void* p) {
    return (unsigned)__cvta_generic_to_shared(p);
}
__device__ __forceinline__ void ldmat4(unsigned& r0, unsigned& r1, unsigned& r2, unsigned& r3, unsigned addr) {
    asm volatile("ldmatrix.sync.aligned.m8n8.x4.shared.b16 {%0,%1,%2,%3}, [%4];"
                 : "=r"(r0), "=r"(r1), "=r"(r2), "=r"(r3) : "r"(addr));
}
__device__ __forceinline__ void ldmat4t(unsigned& r0, unsigned& r1, unsigned& r2, unsigned& r3, unsigned addr) {
    asm volatile("ldmatrix.sync.aligned.m8n8.x4.trans.shared.b16 {%0,%1,%2,%3}, [%4];"
                 : "=r"(r0), "=r"(r1), "=r"(r2), "=r"(r3) : "r"(addr));
}
__device__ __forceinline__ void mma16816(float* c, const unsigned* a, unsigned b0, unsigned b1) {
    asm volatile("mma.sync.aligned.m16n8k16.row.col.f32.f16.f16.f32 "
                 "{%0,%1,%2,%3}, {%4,%5,%6,%7}, {%8,%9}, {%0,%1,%2,%3};"
                 : "+f"(c[0]), "+f"(c[1]), "+f"(c[2]), "+f"(c[3])
                 : "r"(a[0]), "r"(a[1]), "r"(a[2]), "r"(a[3]), "r"(b0), "r"(b1));
}

// -------- fp32 -> fp16 converts --------
__global__ void k_cvtX(const float* __restrict__ x) {
    int i = blockIdx.x * blockDim.x + threadIdx.x;
    if (i >= N_NODES * F_IN / 4) return;
    float4 v = ((const float4*)x)[i];
    __half2 a = __floats2half2_rn(v.x, v.y);
    __half2 b = __floats2half2_rn(v.z, v.w);
    uint2 st; st.x = *(unsigned*)&a; st.y = *(unsigned*)&b;
    ((uint2*)g_xh)[i] = st;
}
__global__ void k_cvtW(const float* __restrict__ w) {
    int i = blockIdx.x * blockDim.x + threadIdx.x;
    if (i >= F_IN * HH / 4) return;
    float4 v = ((const float4*)w)[i];
    __half2 a = __floats2half2_rn(v.x, v.y);
    __half2 b = __floats2half2_rn(v.z, v.w);
    uint2 st; st.x = *(unsigned*)&a; st.y = *(unsigned*)&b;
    ((uint2*)g_w1h)[i] = st;
}

// -------- zero degree counters (deg=1 seeds the self loop) --------
__global__ void k_zero() {
    int i = blockIdx.x * blockDim.x + threadIdx.x;
    if (i < N_NODES) { g_deg[i] = 1; g_cur[i] = 0; }
}

// -------- detect int64 vs int32 edge_index layout --------
__global__ void k_detect(const int* __restrict__ ei32) {
    __shared__ int nz;
    if (threadIdx.x == 0) nz = 0;
    __syncthreads();
    int c = 0;
    for (int i = threadIdx.x; i < 1024; i += blockDim.x)
        if (ei32[2*i + 1] != 0) c++;
    atomicAdd(&nz, c);
    __syncthreads();
    if (threadIdx.x == 0) g_fmt64 = (nz == 0) ? 1 : 0;
}

// -------- init: convert edges to int32 AND count in-degrees --------
__global__ void k_init(const void* __restrict__ ei) {
    int i = blockIdx.x * blockDim.x + threadIdx.x;
    if (i >= N_EDGES) return;
    int s, d;
    if (g_fmt64) {
        const long long* e = (const long long*)ei;
        s = (int)e[i];
        d = (int)e[N_EDGES + i];
    } else {
        const int* e = (const int*)ei;
        s = e[i];
        d = e[N_EDGES + i];
    }
    g_src[i] = s;
    g_dst[i] = d;
    atomicAdd(&g_deg[d], 1);
}

// -------- scan (3 stages) --------
__global__ void k_scan1() {
    __shared__ int s[SCAN_BLK];
    int t = threadIdx.x;
    int i = blockIdx.x * SCAN_BLK + t;
    int v = (i < N_NODES) ? g_deg[i] : 0;
    s[t] = v;
    __syncthreads();
    for (int off = 1; off < SCAN_BLK; off <<= 1) {
        int x = (t >= off) ? s[t - off] : 0;
        __syncthreads();
        s[t] += x;
        __syncthreads();
    }
    if (i < N_NODES) g_scan[i] = s[t] - v;
    if (t == SCAN_BLK - 1) g_bsum[blockIdx.x] = s[t];
}

__global__ void k_scan2() {
    __shared__ int s[128];
    int t = threadIdx.x;
    int v = (t < NB) ? g_bsum[t] : 0;
    s[t] = v;
    __syncthreads();
    for (int off = 1; off < 128; off <<= 1) {
        int x = (t >= off) ? s[t - off] : 0;
        __syncthreads();
        s[t] += x;
        __syncthreads();
    }
    if (t < NB) g_boff[t] = s[t] - v;
}

__global__ void k_scan3() {
    int i = blockIdx.x * blockDim.x + threadIdx.x;
    if (i < N_NODES) g_off[i] = g_scan[i] + g_boff[i / SCAN_BLK];
}

__global__ void k_fill() {
    int i = blockIdx.x * blockDim.x + threadIdx.x;
    if (i >= ET) return;
    int s, d;
    if (i < N_EDGES) { s = g_src[i]; d = g_dst[i]; }
    else             { s = d = i - N_EDGES; }
    int pos = atomicAdd(&g_cur[d], 1);
    g_adj[g_off[d] + pos] = s;
}

// -------- tensor-core GEMM: h1[M,256] = xh[M,128] @ w1h[128,256] --------
// block tile 128x128, 8 warps (4 along M x 2 along N), K staged 64
#define APAD 72    // 64 + 8 halves padded row stride (A stage tile)
#define BPAD 136   // 128 + 8 halves padded row stride (B stage tile)
__global__ void __launch_bounds__(256, 2)
k_mma(const float* __restrict__ attS, const float* __restrict__ attD) {
    __shared__ __half As[128][APAD];
    __shared__ __half Bs[64][BPAD];
    const int t    = threadIdx.x;
    const int lane = t & 31;
    const int wid  = t >> 5;
    const int wm   = wid & 3;            // warp row: 32 rows each
    const int wn   = wid >> 2;           // warp col: 64 cols each
    const int bm   = blockIdx.x * 128;
    const int bn   = blockIdx.y * 128;

    float acc[2][8][4];
#pragma unroll
    for (int i = 0; i < 2; i++)
#pragma unroll
        for (int j = 0; j < 8; j++)
#pragma unroll
            for (int k = 0; k < 4; k++) acc[i][j][k] = 0.f;

    const int quad = lane >> 3;
    for (int kt = 0; kt < F_IN; kt += 64) {
        // load A stage: 128 rows x 64 halves = 1024 chunks of 16B (8 chunks/row)
#pragma unroll
        for (int it = 0; it < 4; it++) {
            int c  = t + it*256;
            int r  = c >> 3, cc = c & 7;
            int gr = bm + r;
            uint4 v = make_uint4(0u, 0u, 0u, 0u);
            if (gr < N_NODES)
                v = *(const uint4*)(g_xh + (size_t)gr*F_IN + kt + cc*8);
            *(uint4*)&As[r][cc*8] = v;
        }
        // load B stage: 64 rows x 128 halves = 1024 chunks of 16B (16 chunks/row)
#pragma unroll
        for (int it = 0; it < 4; it++) {
            int c  = t + it*256;
            int kr = c >> 4, cc = c & 15;
            uint4 v = *(const uint4*)(g_w1h + (size_t)(kt+kr)*HH + bn + cc*8);
            *(uint4*)&Bs[kr][cc*8] = v;
        }
        __syncthreads();
#pragma unroll
        for (int ks = 0; ks < 4; ks++) {
            unsigned a[2][4];
#pragma unroll
            for (int mi = 0; mi < 2; mi++) {
                int row = wm*32 + mi*16 + (lane & 7) + (quad & 1)*8;
                int col = ks*16 + (quad >> 1)*8;
                ldmat4(a[mi][0], a[mi][1], a[mi][2], a[mi][3],
                       s2u(&As[row][col]));
            }
            unsigned b[4][4];
#pragma unroll
            for (int ni = 0; ni < 4; ni++) {
                int krow = ks*16 + (lane & 7) + (quad & 1)*8;
                int col  = wn*64 + ni*16 + (quad >> 1)*8;
                ldmat4t(b[ni][0], b[ni][1], b[ni][2], b[ni][3],
                        s2u(&Bs[krow][col]));
            }
#pragma unroll
            for (int mi = 0; mi < 2; mi++)
#pragma unroll
                for (int ni = 0; ni < 4; ni++) {
                    mma16816(acc[mi][ni*2],   a[mi], b[ni][0], b[ni][1]);
                    mma16816(acc[mi][ni*2+1], a[mi], b[ni][2], b[ni][3]);
                }
        }
        __syncthreads();
    }

    // epilogue: fp16 h1 store + fused attention dots (fp32)
    const int head = (bn >> 6) + wn;
#pragma unroll
    for (int mi = 0; mi < 2; mi++) {
        int r0 = bm + wm*32 + mi*16 + (lane >> 2);   // rows r0 and r0+8
        float pS0 = 0.f, pD0 = 0.f, pS8 = 0.f, pD8 = 0.f;
#pragma unroll
        for (int nj = 0; nj < 8; nj++) {
            int col = bn + wn*64 + nj*8 + (lane & 3)*2;
            float c0 = acc[mi][nj][0], c1 = acc[mi][nj][1];
            float c2 = acc[mi][nj][2], c3 = acc[mi][nj][3];
            float sS0 = attS[col], sS1 = attS[col+1];
            float sD0 = attD[col], sD1 = attD[col+1];
            pS0 += c0*sS0 + c1*sS1;  pD0 += c0*sD0 + c1*sD1;
            pS8 += c2*sS0 + c3*sS1;  pD8 += c2*sD0 + c3*sD1;
            if (r0 < N_NODES) {
                __half2 h0 = __floats2half2_rn(c0, c1);
                g_h1h[(size_t)r0*128 + (col >> 1)] = h0;
            }
            if (r0 + 8 < N_NODES) {
                __half2 h8 = __floats2half2_rn(c2, c3);
                g_h1h[(size_t)(r0+8)*128 + (col >> 1)] = h8;
            }
        }
        // reduce over the 4 lanes of the quad (same rows)
#pragma unroll
        for (int o = 1; o <= 2; o <<= 1) {
            pS0 += __shfl_xor_sync(0xffffffffu, pS0, o);
            pD0 += __shfl_xor_sync(0xffffffffu, pD0, o);
            pS8 += __shfl_xor_sync(0xffffffffu, pS8, o);
            pD8 += __shfl_xor_sync(0xffffffffu, pD8, o);
        }
        if ((lane & 3) == 0) {
            if (r0 < N_NODES)     { g_as1[r0*4 + head]     = pS0; g_ad1[r0*4 + head]     = pD0; }
            if (r0 + 8 < N_NODES) { g_as1[(r0+8)*4 + head] = pS8; g_ad1[(r0+8)*4 + head] = pD8; }
        }
    }
}

// -------- fused layer1: softmax + aggregation + ELU + layer2 GEMV ----------
__global__ void k_fused1(const float* __restrict__ b1, const float* __restrict__ W2,
                         const float* __restrict__ attS2, const float* __restrict__ attD2) {
    int w    = (blockIdx.x * blockDim.x + threadIdx.x) >> 5;
    int lane = threadIdx.x & 31;
    if (w >= N_NODES) return;
    const int beg = g_off[w];
    const int end = beg + g_deg[w];
    float4 ad = *(const float4*)(g_ad1 + w*4);

    const int hd = lane >> 3;            // head of this lane's channels [lane*8 .. +7]
    float acc0=0.f,acc1=0.f,acc2=0.f,acc3=0.f,acc4=0.f,acc5=0.f,acc6=0.f,acc7=0.f;
    float4 zs = make_float4(0.f, 0.f, 0.f, 0.f);
    for (int base = beg; base < end; base += 32) {
        int j = base + lane;
        int s = 0;
        float4 ex = make_float4(0.f, 0.f, 0.f, 0.f);
        if (j < end) {
            s = g_adj[j];
            float4 as = *(const float4*)(g_as1 + s*4);
            ex.x = __expf(lrelu(as.x + ad.x));
            ex.y = __expf(lrelu(as.y + ad.y));
            ex.z = __expf(lrelu(as.z + ad.z));
            ex.w = __expf(lrelu(as.w + ad.w));
            zs.x += ex.x; zs.y += ex.y; zs.z += ex.z; zs.w += ex.w;
        }
        int cnt = min(32, end - base);
        for (int jj = 0; jj < cnt; jj++) {
            int   ss = __shfl_sync(0xffffffffu, s, jj);
            float e0 = __shfl_sync(0xffffffffu, ex.x, jj);
            float e1 = __shfl_sync(0xffffffffu, ex.y, jj);
            float e2 = __shfl_sync(0xffffffffu, ex.z, jj);
            float e3 = __shfl_sync(0xffffffffu, ex.w, jj);
            float eh = (hd == 0) ? e0 : (hd == 1) ? e1 : (hd == 2) ? e2 : e3;
            float4 hv = *((const float4*)g_h1h + (size_t)ss*32 + lane);
            const __half2* ph = (const __half2*)&hv;
            float2 q0 = __half22float2(ph[0]);
            float2 q1 = __half22float2(ph[1]);
            float2 q2 = __half22float2(ph[2]);
            float2 q3 = __half22float2(ph[3]);
            acc0 += eh*q0.x; acc1 += eh*q0.y;
            acc2 += eh*q1.x; acc3 += eh*q1.y;
            acc4 += eh*q2.x; acc5 += eh*q2.y;
            acc6 += eh*q3.x; acc7 += eh*q3.y;
        }
    }
#pragma unroll
    for (int o = 16; o >= 1; o >>= 1) {
        zs.x += __shfl_xor_sync(0xffffffffu, zs.x, o);
        zs.y += __shfl_xor_sync(0xffffffffu, zs.y, o);
        zs.z += __shfl_xor_sync(0xffffffffu, zs.z, o);
        zs.w += __shfl_xor_sync(0xffffffffu, zs.w, o);
    }
    float zh = (hd == 0) ? zs.x : (hd == 1) ? zs.y : (hd == 2) ? zs.z : zs.w;
    float4 bA = *(const float4*)(b1 + lane*8);
    float4 bB = *(const float4*)(b1 + lane*8 + 4);
    float o0 = acc0/zh + bA.x, o1 = acc1/zh + bA.y;
    float o2 = acc2/zh + bA.z, o3 = acc3/zh + bA.w;
    float o4 = acc4/zh + bB.x, o5 = acc5/zh + bB.y;
    float o6 = acc6/zh + bB.z, o7 = acc7/zh + bB.w;
    o0 = o0 > 0.f ? o0 : (__expf(o0) - 1.f);
    o1 = o1 > 0.f ? o1 : (__expf(o1) - 1.f);
    o2 = o2 > 0.f ? o2 : (__expf(o2) - 1.f);
    o3 = o3 > 0.f ? o3 : (__expf(o3) - 1.f);
    o4 = o4 > 0.f ? o4 : (__expf(o4) - 1.f);
    o5 = o5 > 0.f ? o5 : (__expf(o5) - 1.f);
    o6 = o6 > 0.f ? o6 : (__expf(o6) - 1.f);
    o7 = o7 > 0.f ? o7 : (__expf(o7) - 1.f);
    // fused layer2 GEMV (256 -> 2): W2 row-major [256][2]
    const float4* Wv = (const float4*)(W2 + lane*16);
    float4 w0 = Wv[0], w1 = Wv[1], w2 = Wv[2], w3 = Wv[3];
    float s0 = o0*w0.x + o1*w0.z + o2*w1.x + o3*w1.z
             + o4*w2.x + o5*w2.z + o6*w3.x + o7*w3.z;
    float s1 = o0*w0.y + o1*w0.w + o2*w1.y + o3*w1.w
             + o4*w2.y + o5*w2.w + o6*w3.y + o7*w3.w;
#pragma unroll
    for (int o = 16; o >= 1; o >>= 1) {
        s0 += __shfl_xor_sync(0xffffffffu, s0, o);
        s1 += __shfl_xor_sync(0xffffffffu, s1, o);
    }
    if (lane == 0) {
        g_h2[w*2]   = s0;
        g_h2[w*2+1] = s1;
        g_as2[w] = s0*attS2[0] + s1*attS2[1];
        g_ad2[w] = s0*attD2[0] + s1*attD2[1];
    }
}

// -------- fused layer2 (thread per dst, single pass) --------
__global__ void k_fused2(float* __restrict__ out, const float* __restrict__ b2) {
    int t = blockIdx.x * blockDim.x + threadIdx.x;
    if (t >= N_NODES) return;
    const int beg = g_off[t];
    const int end = beg + g_deg[t];
    const float ad = g_ad2[t];
    float z = 0.f, a0 = 0.f, a1 = 0.f;
    for (int j = beg; j < end; j++) {
        int s = g_adj[j];
        float ex = __expf(lrelu(g_as2[s] + ad));
        z  += ex;
        a0 += ex * g_h2[2*s];
        a1 += ex * g_h2[2*s+1];
    }
    out[2*t]   = a0 / z + b2[0];
    out[2*t+1] = a1 / z + b2[1];
}

extern "C" void kernel_launch(void* const* d_in, const int* in_sizes, int n_in,
                              void* d_out, int out_size) {
    const float* x    = (const float*)d_in[0];
    const void*  ei   = d_in[1];
    const float* W1   = (const float*)d_in[2];
    const float* aS1  = (const float*)d_in[3];
    const float* aD1  = (const float*)d_in[4];
    const float* b1   = (const float*)d_in[5];
    const float* W2   = (const float*)d_in[6];
    const float* aS2  = (const float*)d_in[7];
    const float* aD2  = (const float*)d_in[8];
    const float* b2   = (const float*)d_in[9];
    float* out = (float*)d_out;

    const int TB = 256;
    k_cvtX<<<(N_NODES*F_IN/4 + TB - 1) / TB, TB>>>(x);         // 0
    k_cvtW<<<(F_IN*HH/4 + TB - 1) / TB, TB>>>(W1);             // 1
    k_zero<<<(N_NODES + TB - 1) / TB, TB>>>();                 // 2
    dim3 gg((N_NODES + 127) / 128, HH / 128);
    k_mma<<<gg, 256>>>(aS1, aD1);                              // 3  <- profiled
    k_detect<<<1, 256>>>((const int*)ei);                      // 4
    k_init<<<(N_EDGES + TB - 1) / TB, TB>>>(ei);               // 5
    k_scan1<<<NB, SCAN_BLK>>>();                               // 6
    k_scan2<<<1, 128>>>();                                     // 7
    k_scan3<<<(N_NODES + TB - 1) / TB, TB>>>();                // 8
    k_fill<<<(ET + TB - 1) / TB, TB>>>();                      // 9
    k_fused1<<<(N_NODES*32 + TB - 1) / TB, TB>>>(b1, W2, aS2, aD2);  // 10
    k_fused2<<<(N_NODES + TB - 1) / TB, TB>>>(out, b2);        // 11
}

// round 9
// speedup vs baseline: 3.0510x; 1.1158x over previous
#include <cuda_runtime.h>
#include <cuda_fp16.h>

#define N_NODES 50000
#define N_EDGES 800000
#define ET (N_EDGES + N_NODES)   // edges + self loops
#define F_IN 128
#define HEADS 4
#define HID 64
#define HH (HEADS*HID)           // 256
#define NEG 0.2f

#define SCAN_BLK 512
#define NB ((N_NODES + SCAN_BLK - 1) / SCAN_BLK)   // 98

// -------- device scratch (static: no allocation allowed) --------
__device__ __align__(16) __half    g_xh[N_NODES*F_IN];    // x in fp16
__device__ __align__(16) __half    g_w1h[F_IN*HH];        // W1 in fp16
__device__ __align__(16) __half2   g_h1h[N_NODES*128];    // layer1 features (fp16)
__device__ __align__(16) float     g_as1[N_NODES*HEADS];
__device__ __align__(16) float     g_ad1[N_NODES*HEADS];
__device__ __align__(16) int       g_deg[N_NODES];
__device__ __align__(16) int       g_cur[N_NODES];
__device__ __align__(16) int       g_scan[N_NODES];
__device__ __align__(16) int       g_off[N_NODES];
__device__ __align__(16) int       g_bsum[NB];
__device__ __align__(16) int       g_boff[NB];
__device__ __align__(16) int       g_adj[ET];             // CSR: src per incoming slot
__device__ __align__(16) float     g_h2[N_NODES*2];
__device__ __align__(16) float     g_as2[N_NODES];
__device__ __align__(16) float     g_ad2[N_NODES];
__device__ int g_fmt64;

__device__ __forceinline__ float lrelu(float x) { return x > 0.f ? x : NEG * x; }

__device__ __forceinline__ unsigned s2u(const void* p) {
    return (unsigned)__cvta_generic_to_shared(p);
}
__device__ __forceinline__ void ldmat4(unsigned& r0, unsigned& r1, unsigned& r2, unsigned& r3, unsigned addr) {
    asm volatile("ldmatrix.sync.aligned.m8n8.x4.shared.b16 {%0,%1,%2,%3}, [%4];"
                 : "=r"(r0), "=r"(r1), "=r"(r2), "=r"(r3) : "r"(addr));
}
__device__ __forceinline__ void ldmat4t(unsigned& r0, unsigned& r1, unsigned& r2, unsigned& r3, unsigned addr) {
    asm volatile("ldmatrix.sync.aligned.m8n8.x4.trans.shared.b16 {%0,%1,%2,%3}, [%4];"
                 : "=r"(r0), "=r"(r1), "=r"(r2), "=r"(r3) : "r"(addr));
}
__device__ __forceinline__ void mma16816(float* c, const unsigned* a, unsigned b0, unsigned b1) {
    asm volatile("mma.sync.aligned.m16n8k16.row.col.f32.f16.f16.f32 "
                 "{%0,%1,%2,%3}, {%4,%5,%6,%7}, {%8,%9}, {%0,%1,%2,%3};"
                 : "+f"(c[0]), "+f"(c[1]), "+f"(c[2]), "+f"(c[3])
                 : "r"(a[0]), "r"(a[1]), "r"(a[2]), "r"(a[3]), "r"(b0), "r"(b1));
}

// -------- zero degree counters (+ block 0: detect edge dtype) --------
__global__ void k_zero(const int* __restrict__ ei32) {
    int i = blockIdx.x * blockDim.x + threadIdx.x;
    if (i < N_NODES) { g_deg[i] = 1; g_cur[i] = 0; }   // deg=1 seeds self loop
    if (blockIdx.x == 0) {
        __shared__ int nz;
        if (threadIdx.x == 0) nz = 0;
        __syncthreads();
        int c = 0;
        for (int k = threadIdx.x; k < 1024; k += blockDim.x)
            if (ei32[2*k + 1] != 0) c++;
        atomicAdd(&nz, c);
        __syncthreads();
        if (threadIdx.x == 0) g_fmt64 = (nz == 0) ? 1 : 0;
    }
}

// -------- fp32 -> fp16 converts (x and W1 in one kernel) --------
#define CVT_X_CHUNKS (N_NODES*F_IN/4)
#define CVT_W_CHUNKS (F_IN*HH/4)
__global__ void k_cvt(const float* __restrict__ x, const float* __restrict__ w) {
    int i = blockIdx.x * blockDim.x + threadIdx.x;
    if (i < CVT_X_CHUNKS) {
        float4 v = ((const float4*)x)[i];
        __half2 a = __floats2half2_rn(v.x, v.y);
        __half2 b = __floats2half2_rn(v.z, v.w);
        uint2 st; st.x = *(unsigned*)&a; st.y = *(unsigned*)&b;
        ((uint2*)g_xh)[i] = st;
    } else if (i < CVT_X_CHUNKS + CVT_W_CHUNKS) {
        int j = i - CVT_X_CHUNKS;
        float4 v = ((const float4*)w)[j];
        __half2 a = __floats2half2_rn(v.x, v.y);
        __half2 b = __floats2half2_rn(v.z, v.w);
        uint2 st; st.x = *(unsigned*)&a; st.y = *(unsigned*)&b;
        ((uint2*)g_w1h)[j] = st;
    }
}

// -------- count in-degrees (reads dst half of edge_index directly) --------
__global__ void k_count(const void* __restrict__ ei) {
    int i = blockIdx.x * blockDim.x + threadIdx.x;
    if (i >= N_EDGES) return;
    int d = g_fmt64 ? (int)((const long long*)ei)[N_EDGES + i]
                    : ((const int*)ei)[N_EDGES + i];
    atomicAdd(&g_deg[d], 1);
}

// -------- scan (3 stages) --------
__global__ void k_scan1() {
    __shared__ int s[SCAN_BLK];
    int t = threadIdx.x;
    int i = blockIdx.x * SCAN_BLK + t;
    int v = (i < N_NODES) ? g_deg[i] : 0;
    s[t] = v;
    __syncthreads();
    for (int off = 1; off < SCAN_BLK; off <<= 1) {
        int x = (t >= off) ? s[t - off] : 0;
        __syncthreads();
        s[t] += x;
        __syncthreads();
    }
    if (i < N_NODES) g_scan[i] = s[t] - v;
    if (t == SCAN_BLK - 1) g_bsum[blockIdx.x] = s[t];
}

__global__ void k_scan2() {
    __shared__ int s[128];
    int t = threadIdx.x;
    int v = (t < NB) ? g_bsum[t] : 0;
    s[t] = v;
    __syncthreads();
    for (int off = 1; off < 128; off <<= 1) {
        int x = (t >= off) ? s[t - off] : 0;
        __syncthreads();
        s[t] += x;
        __syncthreads();
    }
    if (t < NB) g_boff[t] = s[t] - v;
}

__global__ void k_scan3() {
    int i = blockIdx.x * blockDim.x + threadIdx.x;
    if (i < N_NODES) g_off[i] = g_scan[i] + g_boff[i / SCAN_BLK];
}

// -------- fill CSR (reads edge_index directly) --------
__global__ void k_fill(const void* __restrict__ ei) {
    int i = blockIdx.x * blockDim.x + threadIdx.x;
    if (i >= ET) return;
    int s, d;
    if (i < N_EDGES) {
        if (g_fmt64) {
            const long long* e = (const long long*)ei;
            s = (int)e[i]; d = (int)e[N_EDGES + i];
        } else {
            const int* e = (const int*)ei;
            s = e[i]; d = e[N_EDGES + i];
        }
    } else s = d = i - N_EDGES;
    int pos = atomicAdd(&g_cur[d], 1);
    g_adj[g_off[d] + pos] = s;
}

// -------- tensor-core GEMM: h1[M,256] = xh[M,128] @ w1h[128,256] --------
#define APAD 72
#define BPAD 136
__global__ void __launch_bounds__(256, 2)
k_mma(const float* __restrict__ attS, const float* __restrict__ attD) {
    __shared__ __half As[128][APAD];
    __shared__ __half Bs[64][BPAD];
    const int t    = threadIdx.x;
    const int lane = t & 31;
    const int wid  = t >> 5;
    const int wm   = wid & 3;
    const int wn   = wid >> 2;
    const int bm   = blockIdx.x * 128;
    const int bn   = blockIdx.y * 128;

    float acc[2][8][4];
#pragma unroll
    for (int i = 0; i < 2; i++)
#pragma unroll
        for (int j = 0; j < 8; j++)
#pragma unroll
            for (int k = 0; k < 4; k++) acc[i][j][k] = 0.f;

    const int quad = lane >> 3;
    for (int kt = 0; kt < F_IN; kt += 64) {
#pragma unroll
        for (int it = 0; it < 4; it++) {
            int c  = t + it*256;
            int r  = c >> 3, cc = c & 7;
            int gr = bm + r;
            uint4 v = make_uint4(0u, 0u, 0u, 0u);
            if (gr < N_NODES)
                v = *(const uint4*)(g_xh + (size_t)gr*F_IN + kt + cc*8);
            *(uint4*)&As[r][cc*8] = v;
        }
#pragma unroll
        for (int it = 0; it < 4; it++) {
            int c  = t + it*256;
            int kr = c >> 4, cc = c & 15;
            uint4 v = *(const uint4*)(g_w1h + (size_t)(kt+kr)*HH + bn + cc*8);
            *(uint4*)&Bs[kr][cc*8] = v;
        }
        __syncthreads();
#pragma unroll
        for (int ks = 0; ks < 4; ks++) {
            unsigned a[2][4];
#pragma unroll
            for (int mi = 0; mi < 2; mi++) {
                int row = wm*32 + mi*16 + (lane & 7) + (quad & 1)*8;
                int col = ks*16 + (quad >> 1)*8;
                ldmat4(a[mi][0], a[mi][1], a[mi][2], a[mi][3], s2u(&As[row][col]));
            }
            unsigned b[4][4];
#pragma unroll
            for (int ni = 0; ni < 4; ni++) {
                int krow = ks*16 + (lane & 7) + (quad & 1)*8;
                int col  = wn*64 + ni*16 + (quad >> 1)*8;
                ldmat4t(b[ni][0], b[ni][1], b[ni][2], b[ni][3], s2u(&Bs[krow][col]));
            }
#pragma unroll
            for (int mi = 0; mi < 2; mi++)
#pragma unroll
                for (int ni = 0; ni < 4; ni++) {
                    mma16816(acc[mi][ni*2],   a[mi], b[ni][0], b[ni][1]);
                    mma16816(acc[mi][ni*2+1], a[mi], b[ni][2], b[ni][3]);
                }
        }
        __syncthreads();
    }

    const int head = (bn >> 6) + wn;
#pragma unroll
    for (int mi = 0; mi < 2; mi++) {
        int r0 = bm + wm*32 + mi*16 + (lane >> 2);
        float pS0 = 0.f, pD0 = 0.f, pS8 = 0.f, pD8 = 0.f;
#pragma unroll
        for (int nj = 0; nj < 8; nj++) {
            int col = bn + wn*64 + nj*8 + (lane & 3)*2;
            float c0 = acc[mi][nj][0], c1 = acc[mi][nj][1];
            float c2 = acc[mi][nj][2], c3 = acc[mi][nj][3];
            float sS0 = attS[col], sS1 = attS[col+1];
            float sD0 = attD[col], sD1 = attD[col+1];
            pS0 += c0*sS0 + c1*sS1;  pD0 += c0*sD0 + c1*sD1;
            pS8 += c2*sS0 + c3*sS1;  pD8 += c2*sD0 + c3*sD1;
            if (r0 < N_NODES)
                g_h1h[(size_t)r0*128 + (col >> 1)] = __floats2half2_rn(c0, c1);
            if (r0 + 8 < N_NODES)
                g_h1h[(size_t)(r0+8)*128 + (col >> 1)] = __floats2half2_rn(c2, c3);
        }
#pragma unroll
        for (int o = 1; o <= 2; o <<= 1) {
            pS0 += __shfl_xor_sync(0xffffffffu, pS0, o);
            pD0 += __shfl_xor_sync(0xffffffffu, pD0, o);
            pS8 += __shfl_xor_sync(0xffffffffu, pS8, o);
            pD8 += __shfl_xor_sync(0xffffffffu, pD8, o);
        }
        if ((lane & 3) == 0) {
            if (r0 < N_NODES)     { g_as1[r0*4 + head]     = pS0; g_ad1[r0*4 + head]     = pD0; }
            if (r0 + 8 < N_NODES) { g_as1[(r0+8)*4 + head] = pS8; g_ad1[(r0+8)*4 + head] = pD8; }
        }
    }
}

// -------- fused layer1: softmax + aggregation + ELU + layer2 GEMV ----------
__global__ void k_fused1(const float* __restrict__ b1, const float* __restrict__ W2,
                         const float* __restrict__ attS2, const float* __restrict__ attD2) {
    int w    = (blockIdx.x * blockDim.x + threadIdx.x) >> 5;
    int lane = threadIdx.x & 31;
    if (w >= N_NODES) return;
    const int beg = g_off[w];
    const int end = beg + g_deg[w];
    float4 ad = *(const float4*)(g_ad1 + w*4);

    const int hd = lane >> 3;
    float acc0=0.f,acc1=0.f,acc2=0.f,acc3=0.f,acc4=0.f,acc5=0.f,acc6=0.f,acc7=0.f;
    float4 zs = make_float4(0.f, 0.f, 0.f, 0.f);
    for (int base = beg; base < end; base += 32) {
        int j = base + lane;
        int s = 0;
        float4 ex = make_float4(0.f, 0.f, 0.f, 0.f);
        if (j < end) {
            s = g_adj[j];
            float4 as = *(const float4*)(g_as1 + s*4);
            ex.x = __expf(lrelu(as.x + ad.x));
            ex.y = __expf(lrelu(as.y + ad.y));
            ex.z = __expf(lrelu(as.z + ad.z));
            ex.w = __expf(lrelu(as.w + ad.w));
            zs.x += ex.x; zs.y += ex.y; zs.z += ex.z; zs.w += ex.w;
        }
        int cnt = min(32, end - base);
        int jj = 0;
        // 4-deep unroll: issue 4 independent gathers before consuming (MLP=4)
        for (; jj + 4 <= cnt; jj += 4) {
            int ss0 = __shfl_sync(0xffffffffu, s, jj);
            int ss1 = __shfl_sync(0xffffffffu, s, jj+1);
            int ss2 = __shfl_sync(0xffffffffu, s, jj+2);
            int ss3 = __shfl_sync(0xffffffffu, s, jj+3);
            float4 hv0 = *((const float4*)g_h1h + (size_t)ss0*32 + lane);
            float4 hv1 = *((const float4*)g_h1h + (size_t)ss1*32 + lane);
            float4 hv2 = *((const float4*)g_h1h + (size_t)ss2*32 + lane);
            float4 hv3 = *((const float4*)g_h1h + (size_t)ss3*32 + lane);
#pragma unroll
            for (int u = 0; u < 4; u++) {
                float e0 = __shfl_sync(0xffffffffu, ex.x, jj+u);
                float e1 = __shfl_sync(0xffffffffu, ex.y, jj+u);
                float e2 = __shfl_sync(0xffffffffu, ex.z, jj+u);
                float e3 = __shfl_sync(0xffffffffu, ex.w, jj+u);
                float eh = (hd == 0) ? e0 : (hd == 1) ? e1 : (hd == 2) ? e2 : e3;
                float4 hv = (u == 0) ? hv0 : (u == 1) ? hv1 : (u == 2) ? hv2 : hv3;
                const __half2* ph = (const __half2*)&hv;
                float2 q0 = __half22float2(ph[0]);
                float2 q1 = __half22float2(ph[1]);
                float2 q2 = __half22float2(ph[2]);
                float2 q3 = __half22float2(ph[3]);
                acc0 += eh*q0.x; acc1 += eh*q0.y;
                acc2 += eh*q1.x; acc3 += eh*q1.y;
                acc4 += eh*q2.x; acc5 += eh*q2.y;
                acc6 += eh*q3.x; acc7 += eh*q3.y;
            }
        }
        for (; jj < cnt; jj++) {
            int   ss = __shfl_sync(0xffffffffu, s, jj);
            float e0 = __shfl_sync(0xffffffffu, ex.x, jj);
            float e1 = __shfl_sync(0xffffffffu, ex.y, jj);
            float e2 = __shfl_sync(0xffffffffu, ex.z, jj);
            float e3 = __shfl_sync(0xffffffffu, ex.w, jj);
            float eh = (hd == 0) ? e0 : (hd == 1) ? e1 : (hd == 2) ? e2 : e3;
            float4 hv = *((const float4*)g_h1h + (size_t)ss*32 + lane);
            const __half2* ph = (const __half2*)&hv;
            float2 q0 = __half22float2(ph[0]);
            float2 q1 = __half22float2(ph[1]);
            float2 q2 = __half22float2(ph[2]);
            float2 q3 = __half22float2(ph[3]);
            acc0 += eh*q0.x; acc1 += eh*q0.y;
            acc2 += eh*q1.x; acc3 += eh*q1.y;
            acc4 += eh*q2.x; acc5 += eh*q2.y;
            acc6 += eh*q3.x; acc7 += eh*q3.y;
        }
    }
#pragma unroll
    for (int o = 16; o >= 1; o >>= 1) {
        zs.x += __shfl_xor_sync(0xffffffffu, zs.x, o);
        zs.y += __shfl_xor_sync(0xffffffffu, zs.y, o);
        zs.z += __shfl_xor_sync(0xffffffffu, zs.z, o);
        zs.w += __shfl_xor_sync(0xffffffffu, zs.w, o);
    }
    float zh = (hd == 0) ? zs.x : (hd == 1) ? zs.y : (hd == 2) ? zs.z : zs.w;
    float4 bA = *(const float4*)(b1 + lane*8);
    float4 bB = *(const float4*)(b1 + lane*8 + 4);
    float o0 = acc0/zh + bA.x, o1 = acc1/zh + bA.y;
    float o2 = acc2/zh + bA.z, o3 = acc3/zh + bA.w;
    float o4 = acc4/zh + bB.x, o5 = acc5/zh + bB.y;
    float o6 = acc6/zh + bB.z, o7 = acc7/zh + bB.w;
    o0 = o0 > 0.f ? o0 : (__expf(o0) - 1.f);
    o1 = o1 > 0.f ? o1 : (__expf(o1) - 1.f);
    o2 = o2 > 0.f ? o2 : (__expf(o2) - 1.f);
    o3 = o3 > 0.f ? o3 : (__expf(o3) - 1.f);
    o4 = o4 > 0.f ? o4 : (__expf(o4) - 1.f);
    o5 = o5 > 0.f ? o5 : (__expf(o5) - 1.f);
    o6 = o6 > 0.f ? o6 : (__expf(o6) - 1.f);
    o7 = o7 > 0.f ? o7 : (__expf(o7) - 1.f);
    const float4* Wv = (const float4*)(W2 + lane*16);
    float4 w0 = Wv[0], w1 = Wv[1], w2 = Wv[2], w3 = Wv[3];
    float s0 = o0*w0.x + o1*w0.z + o2*w1.x + o3*w1.z
             + o4*w2.x + o5*w2.z + o6*w3.x + o7*w3.z;
    float s1 = o0*w0.y + o1*w0.w + o2*w1.y + o3*w1.w
             + o4*w2.y + o5*w2.w + o6*w3.y + o7*w3.w;
#pragma unroll
    for (int o = 16; o >= 1; o >>= 1) {
        s0 += __shfl_xor_sync(0xffffffffu, s0, o);
        s1 += __shfl_xor_sync(0xffffffffu, s1, o);
    }
    if (lane == 0) {
        g_h2[w*2]   = s0;
        g_h2[w*2+1] = s1;
        g_as2[w] = s0*attS2[0] + s1*attS2[1];
        g_ad2[w] = s0*attD2[0] + s1*attD2[1];
    }
}

// -------- fused layer2 (thread per dst, 4-deep MLP unroll) --------
__global__ void k_fused2(float* __restrict__ out, const float* __restrict__ b2) {
    int t = blockIdx.x * blockDim.x + threadIdx.x;
    if (t >= N_NODES) return;
    const int beg = g_off[t];
    const int end = beg + g_deg[t];
    const float ad = g_ad2[t];
    float z = 0.f, a0 = 0.f, a1 = 0.f;
    int j = beg;
    for (; j + 4 <= end; j += 4) {
        int s0 = g_adj[j], s1 = g_adj[j+1], s2 = g_adj[j+2], s3 = g_adj[j+3];
        float q0 = g_as2[s0], q1 = g_as2[s1], q2 = g_as2[s2], q3 = g_as2[s3];
        float2 h0 = *(const float2*)(g_h2 + 2*s0);
        float2 h1 = *(const float2*)(g_h2 + 2*s1);
        float2 h2 = *(const float2*)(g_h2 + 2*s2);
        float2 h3 = *(const float2*)(g_h2 + 2*s3);
        float e0 = __expf(lrelu(q0 + ad));
        float e1 = __expf(lrelu(q1 + ad));
        float e2 = __expf(lrelu(q2 + ad));
        float e3 = __expf(lrelu(q3 + ad));
        z  += e0 + e1 + e2 + e3;
        a0 += e0*h0.x + e1*h1.x + e2*h2.x + e3*h3.x;
        a1 += e0*h0.y + e1*h1.y + e2*h2.y + e3*h3.y;
    }
    for (; j < end; j++) {
        int s = g_adj[j];
        float ex = __expf(lrelu(g_as2[s] + ad));
        float2 h = *(const float2*)(g_h2 + 2*s);
        z  += ex;
        a0 += ex * h.x;
        a1 += ex * h.y;
    }
    out[2*t]   = a0 / z + b2[0];
    out[2*t+1] = a1 / z + b2[1];
}

extern "C" void kernel_launch(void* const* d_in, const int* in_sizes, int n_in,
                              void* d_out, int out_size) {
    const float* x    = (const float*)d_in[0];
    const void*  ei   = d_in[1];
    const float* W1   = (const float*)d_in[2];
    const float* aS1  = (const float*)d_in[3];
    const float* aD1  = (const float*)d_in[4];
    const float* b1   = (const float*)d_in[5];
    const float* W2   = (const float*)d_in[6];
    const float* aS2  = (const float*)d_in[7];
    const float* aD2  = (const float*)d_in[8];
    const float* b2   = (const float*)d_in[9];
    float* out = (float*)d_out;

    const int TB = 256;
    k_zero<<<(N_NODES + TB - 1) / TB, TB>>>((const int*)ei);                 // 0
    k_cvt<<<(CVT_X_CHUNKS + CVT_W_CHUNKS + TB - 1) / TB, TB>>>(x, W1);       // 1
    k_count<<<(N_EDGES + TB - 1) / TB, TB>>>(ei);                            // 2
    dim3 gg((N_NODES + 127) / 128, HH / 128);
    k_mma<<<gg, 256>>>(aS1, aD1);                                            // 3 <- profiled
    k_scan1<<<NB, SCAN_BLK>>>();                                             // 4
    k_scan2<<<1, 128>>>();                                                   // 5
    k_scan3<<<(N_NODES + TB - 1) / TB, TB>>>();                              // 6
    k_fill<<<(ET + TB - 1) / TB, TB>>>(ei);                                  // 7
    k_fused1<<<(N_NODES*32 + TB - 1) / TB, TB>>>(b1, W2, aS2, aD2);          // 8
    k_fused2<<<(N_NODES + TB - 1) / TB, TB>>>(out, b2);                      // 9
}

// round 10
// speedup vs baseline: 3.6816x; 1.2067x over previous
#include <cuda_runtime.h>
#include <cuda_fp16.h>

#define N_NODES 50000
#define N_EDGES 800000
#define ET (N_EDGES + N_NODES)   // edges + self loops
#define F_IN 128
#define HEADS 4
#define HID 64
#define HH (HEADS*HID)           // 256
#define NEG 0.2f

#define SCAN_BLK 512
#define NB ((N_NODES + SCAN_BLK - 1) / SCAN_BLK)   // 98

// -------- device scratch (static: no allocation allowed) --------
__device__ __align__(16) __half    g_xh[N_NODES*F_IN];    // x in fp16
__device__ __align__(16) __half    g_w1h[F_IN*HH];        // W1 in fp16
__device__ __align__(16) __half2   g_h1h[N_NODES*128];    // layer1 features (fp16)
__device__ __align__(16) float     g_as1[N_NODES*HEADS];
__device__ __align__(16) float     g_ad1[N_NODES*HEADS];
__device__ __align__(16) int       g_deg[N_NODES];
__device__ __align__(16) int       g_cur[N_NODES];
__device__ __align__(16) int       g_scan[N_NODES];
__device__ __align__(16) int       g_off[N_NODES];
__device__ __align__(16) int       g_bsum[NB];
__device__ __align__(16) int       g_boff[NB];
__device__ __align__(16) int       g_adj[ET];             // CSR: src per incoming slot
__device__ __align__(16) float     g_h2[N_NODES*2];
__device__ __align__(16) float     g_as2[N_NODES];
__device__ __align__(16) float     g_ad2[N_NODES];
__device__ int g_fmt64;

__device__ __forceinline__ float lrelu(float x) { return x > 0.f ? x : NEG * x; }

__device__ __forceinline__ unsigned s2u(const void* p) {
    return (unsigned)__cvta_generic_to_shared(p);
}
__device__ __forceinline__ void ldmat4(unsigned& r0, unsigned& r1, unsigned& r2, unsigned& r3, unsigned addr) {
    asm volatile("ldmatrix.sync.aligned.m8n8.x4.shared.b16 {%0,%1,%2,%3}, [%4];"
                 : "=r"(r0), "=r"(r1), "=r"(r2), "=r"(r3) : "r"(addr));
}
__device__ __forceinline__ void ldmat4t(unsigned& r0, unsigned& r1, unsigned& r2, unsigned& r3, unsigned addr) {
    asm volatile("ldmatrix.sync.aligned.m8n8.x4.trans.shared.b16 {%0,%1,%2,%3}, [%4];"
                 : "=r"(r0), "=r"(r1), "=r"(r2), "=r"(r3) : "r"(addr));
}
__device__ __forceinline__ void mma16816(float* c, const unsigned* a, unsigned b0, unsigned b1) {
    asm volatile("mma.sync.aligned.m16n8k16.row.col.f32.f16.f16.f32 "
                 "{%0,%1,%2,%3}, {%4,%5,%6,%7}, {%8,%9}, {%0,%1,%2,%3};"
                 : "+f"(c[0]), "+f"(c[1]), "+f"(c[2]), "+f"(c[3])
                 : "r"(a[0]), "r"(a[1]), "r"(a[2]), "r"(a[3]), "r"(b0), "r"(b1));
}

// -------- zero degree counters (+ block 0: detect edge dtype) --------
__global__ void k_zero(const int* __restrict__ ei32) {
    int i = blockIdx.x * blockDim.x + threadIdx.x;
    if (i < N_NODES) { g_deg[i] = 1; g_cur[i] = 0; }   // deg=1 seeds self loop
    if (blockIdx.x == 0) {
        __shared__ int nz;
        if (threadIdx.x == 0) nz = 0;
        __syncthreads();
        int c = 0;
        for (int k = threadIdx.x; k < 1024; k += blockDim.x)
            if (ei32[2*k + 1] != 0) c++;
        atomicAdd(&nz, c);
        __syncthreads();
        if (threadIdx.x == 0) g_fmt64 = (nz == 0) ? 1 : 0;
    }
}

// -------- fp32 -> fp16 converts (x and W1 in one kernel) --------
#define CVT_X_CHUNKS (N_NODES*F_IN/4)
#define CVT_W_CHUNKS (F_IN*HH/4)
__global__ void k_cvt(const float* __restrict__ x, const float* __restrict__ w) {
    int i = blockIdx.x * blockDim.x + threadIdx.x;
    if (i < CVT_X_CHUNKS) {
        float4 v = ((const float4*)x)[i];
        __half2 a = __floats2half2_rn(v.x, v.y);
        __half2 b = __floats2half2_rn(v.z, v.w);
        uint2 st; st.x = *(unsigned*)&a; st.y = *(unsigned*)&b;
        ((uint2*)g_xh)[i] = st;
    } else if (i < CVT_X_CHUNKS + CVT_W_CHUNKS) {
        int j = i - CVT_X_CHUNKS;
        float4 v = ((const float4*)w)[j];
        __half2 a = __floats2half2_rn(v.x, v.y);
        __half2 b = __floats2half2_rn(v.z, v.w);
        uint2 st; st.x = *(unsigned*)&a; st.y = *(unsigned*)&b;
        ((uint2*)g_w1h)[j] = st;
    }
}

// -------- count in-degrees (reads dst half of edge_index directly) --------
__global__ void k_count(const void* __restrict__ ei) {
    int i = blockIdx.x * blockDim.x + threadIdx.x;
    if (i >= N_EDGES) return;
    int d = g_fmt64 ? (int)((const long long*)ei)[N_EDGES + i]
                    : ((const int*)ei)[N_EDGES + i];
    atomicAdd(&g_deg[d], 1);
}

// -------- scan (3 stages) --------
__global__ void k_scan1() {
    __shared__ int s[SCAN_BLK];
    int t = threadIdx.x;
    int i = blockIdx.x * SCAN_BLK + t;
    int v = (i < N_NODES) ? g_deg[i] : 0;
    s[t] = v;
    __syncthreads();
    for (int off = 1; off < SCAN_BLK; off <<= 1) {
        int x = (t >= off) ? s[t - off] : 0;
        __syncthreads();
        s[t] += x;
        __syncthreads();
    }
    if (i < N_NODES) g_scan[i] = s[t] - v;
    if (t == SCAN_BLK - 1) g_bsum[blockIdx.x] = s[t];
}

__global__ void k_scan2() {
    __shared__ int s[128];
    int t = threadIdx.x;
    int v = (t < NB) ? g_bsum[t] : 0;
    s[t] = v;
    __syncthreads();
    for (int off = 1; off < 128; off <<= 1) {
        int x = (t >= off) ? s[t - off] : 0;
        __syncthreads();
        s[t] += x;
        __syncthreads();
    }
    if (t < NB) g_boff[t] = s[t] - v;
}

__global__ void k_scan3() {
    int i = blockIdx.x * blockDim.x + threadIdx.x;
    if (i < N_NODES) g_off[i] = g_scan[i] + g_boff[i / SCAN_BLK];
}

// -------- fill CSR (reads edge_index directly) --------
__global__ void k_fill(const void* __restrict__ ei) {
    int i = blockIdx.x * blockDim.x + threadIdx.x;
    if (i >= ET) return;
    int s, d;
    if (i < N_EDGES) {
        if (g_fmt64) {
            const long long* e = (const long long*)ei;
            s = (int)e[i]; d = (int)e[N_EDGES + i];
        } else {
            const int* e = (const int*)ei;
            s = e[i]; d = e[N_EDGES + i];
        }
    } else s = d = i - N_EDGES;
    int pos = atomicAdd(&g_cur[d], 1);
    g_adj[g_off[d] + pos] = s;
}

// -------- tensor-core GEMM: h1[M,256] = xh[M,128] @ w1h[128,256] --------
#define APAD 72
#define BPAD 136
__global__ void __launch_bounds__(256, 2)
k_mma(const float* __restrict__ attS, const float* __restrict__ attD) {
    __shared__ __half As[128][APAD];
    __shared__ __half Bs[64][BPAD];
    const int t    = threadIdx.x;
    const int lane = t & 31;
    const int wid  = t >> 5;
    const int wm   = wid & 3;
    const int wn   = wid >> 2;
    const int bm   = blockIdx.x * 128;
    const int bn   = blockIdx.y * 128;

    float acc[2][8][4];
#pragma unroll
    for (int i = 0; i < 2; i++)
#pragma unroll
        for (int j = 0; j < 8; j++)
#pragma unroll
            for (int k = 0; k < 4; k++) acc[i][j][k] = 0.f;

    const int quad = lane >> 3;
    for (int kt = 0; kt < F_IN; kt += 64) {
#pragma unroll
        for (int it = 0; it < 4; it++) {
            int c  = t + it*256;
            int r  = c >> 3, cc = c & 7;
            int gr = bm + r;
            uint4 v = make_uint4(0u, 0u, 0u, 0u);
            if (gr < N_NODES)
                v = *(const uint4*)(g_xh + (size_t)gr*F_IN + kt + cc*8);
            *(uint4*)&As[r][cc*8] = v;
        }
#pragma unroll
        for (int it = 0; it < 4; it++) {
            int c  = t + it*256;
            int kr = c >> 4, cc = c & 15;
            uint4 v = *(const uint4*)(g_w1h + (size_t)(kt+kr)*HH + bn + cc*8);
            *(uint4*)&Bs[kr][cc*8] = v;
        }
        __syncthreads();
#pragma unroll
        for (int ks = 0; ks < 4; ks++) {
            unsigned a[2][4];
#pragma unroll
            for (int mi = 0; mi < 2; mi++) {
                int row = wm*32 + mi*16 + (lane & 7) + (quad & 1)*8;
                int col = ks*16 + (quad >> 1)*8;
                ldmat4(a[mi][0], a[mi][1], a[mi][2], a[mi][3], s2u(&As[row][col]));
            }
            unsigned b[4][4];
#pragma unroll
            for (int ni = 0; ni < 4; ni++) {
                int krow = ks*16 + (lane & 7) + (quad & 1)*8;
                int col  = wn*64 + ni*16 + (quad >> 1)*8;
                ldmat4t(b[ni][0], b[ni][1], b[ni][2], b[ni][3], s2u(&Bs[krow][col]));
            }
#pragma unroll
            for (int mi = 0; mi < 2; mi++)
#pragma unroll
                for (int ni = 0; ni < 4; ni++) {
                    mma16816(acc[mi][ni*2],   a[mi], b[ni][0], b[ni][1]);
                    mma16816(acc[mi][ni*2+1], a[mi], b[ni][2], b[ni][3]);
                }
        }
        __syncthreads();
    }

    const int head = (bn >> 6) + wn;
#pragma unroll
    for (int mi = 0; mi < 2; mi++) {
        int r0 = bm + wm*32 + mi*16 + (lane >> 2);
        float pS0 = 0.f, pD0 = 0.f, pS8 = 0.f, pD8 = 0.f;
#pragma unroll
        for (int nj = 0; nj < 8; nj++) {
            int col = bn + wn*64 + nj*8 + (lane & 3)*2;
            float c0 = acc[mi][nj][0], c1 = acc[mi][nj][1];
            float c2 = acc[mi][nj][2], c3 = acc[mi][nj][3];
            float sS0 = attS[col], sS1 = attS[col+1];
            float sD0 = attD[col], sD1 = attD[col+1];
            pS0 += c0*sS0 + c1*sS1;  pD0 += c0*sD0 + c1*sD1;
            pS8 += c2*sS0 + c3*sS1;  pD8 += c2*sD0 + c3*sD1;
            if (r0 < N_NODES)
                g_h1h[(size_t)r0*128 + (col >> 1)] = __floats2half2_rn(c0, c1);
            if (r0 + 8 < N_NODES)
                g_h1h[(size_t)(r0+8)*128 + (col >> 1)] = __floats2half2_rn(c2, c3);
        }
#pragma unroll
        for (int o = 1; o <= 2; o <<= 1) {
            pS0 += __shfl_xor_sync(0xffffffffu, pS0, o);
            pD0 += __shfl_xor_sync(0xffffffffu, pD0, o);
            pS8 += __shfl_xor_sync(0xffffffffu, pS8, o);
            pD8 += __shfl_xor_sync(0xffffffffu, pD8, o);
        }
        if ((lane & 3) == 0) {
            if (r0 < N_NODES)     { g_as1[r0*4 + head]     = pS0; g_ad1[r0*4 + head]     = pD0; }
            if (r0 + 8 < N_NODES) { g_as1[(r0+8)*4 + head] = pS8; g_ad1[(r0+8)*4 + head] = pD8; }
        }
    }
}

// accumulate 8 fp16 channels of one src row, weighted
__device__ __forceinline__ void agg8(float4 hv, float eh, float* acc) {
    const __half2* ph = (const __half2*)&hv;
    float2 q0 = __half22float2(ph[0]);
    float2 q1 = __half22float2(ph[1]);
    float2 q2 = __half22float2(ph[2]);
    float2 q3 = __half22float2(ph[3]);
    acc[0] += eh*q0.x; acc[1] += eh*q0.y;
    acc[2] += eh*q1.x; acc[3] += eh*q1.y;
    acc[4] += eh*q2.x; acc[5] += eh*q2.y;
    acc[6] += eh*q3.x; acc[7] += eh*q3.y;
}

// -------- fused layer1: softmax + aggregation + ELU + layer2 GEMV ----------
// warp per dst node; smem-staged edge batches; 8-deep MLP gather
__global__ void k_fused1(const float* __restrict__ b1, const float* __restrict__ W2,
                         const float* __restrict__ attS2, const float* __restrict__ attD2) {
    __shared__ __align__(16) int   sid[8][32];
    __shared__ __align__(16) float sex[8][4][32];
    int w     = (blockIdx.x * blockDim.x + threadIdx.x) >> 5;
    int lane  = threadIdx.x & 31;
    int wwarp = threadIdx.x >> 5;
    if (w >= N_NODES) return;
    const int beg = g_off[w];
    const int end = beg + g_deg[w];
    float4 ad = *(const float4*)(g_ad1 + w*4);

    const int hd = lane >> 3;            // head of this lane's channels [lane*8 .. +7]
    float acc[8] = {0.f,0.f,0.f,0.f,0.f,0.f,0.f,0.f};
    float4 zs = make_float4(0.f, 0.f, 0.f, 0.f);
    const float4* hp = (const float4*)g_h1h;

    for (int base = beg; base < end; base += 32) {
        int j = base + lane;
        int s = 0;
        float4 ex = make_float4(0.f, 0.f, 0.f, 0.f);
        if (j < end) {
            s = g_adj[j];
            float4 as = *(const float4*)(g_as1 + s*4);
            ex.x = __expf(lrelu(as.x + ad.x));
            ex.y = __expf(lrelu(as.y + ad.y));
            ex.z = __expf(lrelu(as.z + ad.z));
            ex.w = __expf(lrelu(as.w + ad.w));
            zs.x += ex.x; zs.y += ex.y; zs.z += ex.z; zs.w += ex.w;
        }
        sid[wwarp][lane]    = s;
        sex[wwarp][0][lane] = ex.x;
        sex[wwarp][1][lane] = ex.y;
        sex[wwarp][2][lane] = ex.z;
        sex[wwarp][3][lane] = ex.w;
        __syncwarp();
        int cnt = min(32, end - base);
        int jj = 0;
        for (; jj + 8 <= cnt; jj += 8) {
            int4 ia = *(const int4*)&sid[wwarp][jj];
            int4 ib = *(const int4*)&sid[wwarp][jj+4];
            float4 wa = *(const float4*)&sex[wwarp][hd][jj];
            float4 wb = *(const float4*)&sex[wwarp][hd][jj+4];
            float4 v0 = hp[(size_t)ia.x*32 + lane];
            float4 v1 = hp[(size_t)ia.y*32 + lane];
            float4 v2 = hp[(size_t)ia.z*32 + lane];
            float4 v3 = hp[(size_t)ia.w*32 + lane];
            float4 v4 = hp[(size_t)ib.x*32 + lane];
            float4 v5 = hp[(size_t)ib.y*32 + lane];
            float4 v6 = hp[(size_t)ib.z*32 + lane];
            float4 v7 = hp[(size_t)ib.w*32 + lane];
            agg8(v0, wa.x, acc); agg8(v1, wa.y, acc);
            agg8(v2, wa.z, acc); agg8(v3, wa.w, acc);
            agg8(v4, wb.x, acc); agg8(v5, wb.y, acc);
            agg8(v6, wb.z, acc); agg8(v7, wb.w, acc);
        }
        for (; jj < cnt; jj++) {
            int   ss = sid[wwarp][jj];
            float eh = sex[wwarp][hd][jj];
            float4 v = hp[(size_t)ss*32 + lane];
            agg8(v, eh, acc);
        }
        __syncwarp();
    }
#pragma unroll
    for (int o = 16; o >= 1; o >>= 1) {
        zs.x += __shfl_xor_sync(0xffffffffu, zs.x, o);
        zs.y += __shfl_xor_sync(0xffffffffu, zs.y, o);
        zs.z += __shfl_xor_sync(0xffffffffu, zs.z, o);
        zs.w += __shfl_xor_sync(0xffffffffu, zs.w, o);
    }
    float zh = (hd == 0) ? zs.x : (hd == 1) ? zs.y : (hd == 2) ? zs.z : zs.w;
    float4 bA = *(const float4*)(b1 + lane*8);
    float4 bB = *(const float4*)(b1 + lane*8 + 4);
    float o0 = acc[0]/zh + bA.x, o1 = acc[1]/zh + bA.y;
    float o2 = acc[2]/zh + bA.z, o3 = acc[3]/zh + bA.w;
    float o4 = acc[4]/zh + bB.x, o5 = acc[5]/zh + bB.y;
    float o6 = acc[6]/zh + bB.z, o7 = acc[7]/zh + bB.w;
    o0 = o0 > 0.f ? o0 : (__expf(o0) - 1.f);
    o1 = o1 > 0.f ? o1 : (__expf(o1) - 1.f);
    o2 = o2 > 0.f ? o2 : (__expf(o2) - 1.f);
    o3 = o3 > 0.f ? o3 : (__expf(o3) - 1.f);
    o4 = o4 > 0.f ? o4 : (__expf(o4) - 1.f);
    o5 = o5 > 0.f ? o5 : (__expf(o5) - 1.f);
    o6 = o6 > 0.f ? o6 : (__expf(o6) - 1.f);
    o7 = o7 > 0.f ? o7 : (__expf(o7) - 1.f);
    const float4* Wv = (const float4*)(W2 + lane*16);
    float4 w0 = Wv[0], w1 = Wv[1], w2 = Wv[2], w3 = Wv[3];
    float s0 = o0*w0.x + o1*w0.z + o2*w1.x + o3*w1.z
             + o4*w2.x + o5*w2.z + o6*w3.x + o7*w3.z;
    float s1 = o0*w0.y + o1*w0.w + o2*w1.y + o3*w1.w
             + o4*w2.y + o5*w2.w + o6*w3.y + o7*w3.w;
#pragma unroll
    for (int o = 16; o >= 1; o >>= 1) {
        s0 += __shfl_xor_sync(0xffffffffu, s0, o);
        s1 += __shfl_xor_sync(0xffffffffu, s1, o);
    }
    if (lane == 0) {
        g_h2[w*2]   = s0;
        g_h2[w*2+1] = s1;
        g_as2[w] = s0*attS2[0] + s1*attS2[1];
        g_ad2[w] = s0*attD2[0] + s1*attD2[1];
    }
}

// -------- fused layer2 (thread per dst, 4-deep MLP unroll) --------
__global__ void k_fused2(float* __restrict__ out, const float* __restrict__ b2) {
    int t = blockIdx.x * blockDim.x + threadIdx.x;
    if (t >= N_NODES) return;
    const int beg = g_off[t];
    const int end = beg + g_deg[t];
    const float ad = g_ad2[t];
    float z = 0.f, a0 = 0.f, a1 = 0.f;
    int j = beg;
    for (; j + 4 <= end; j += 4) {
        int s0 = g_adj[j], s1 = g_adj[j+1], s2 = g_adj[j+2], s3 = g_adj[j+3];
        float q0 = g_as2[s0], q1 = g_as2[s1], q2 = g_as2[s2], q3 = g_as2[s3];
        float2 h0 = *(const float2*)(g_h2 + 2*s0);
        float2 h1 = *(const float2*)(g_h2 + 2*s1);
        float2 h2 = *(const float2*)(g_h2 + 2*s2);
        float2 h3 = *(const float2*)(g_h2 + 2*s3);
        float e0 = __expf(lrelu(q0 + ad));
        float e1 = __expf(lrelu(q1 + ad));
        float e2 = __expf(lrelu(q2 + ad));
        float e3 = __expf(lrelu(q3 + ad));
        z  += e0 + e1 + e2 + e3;
        a0 += e0*h0.x + e1*h1.x + e2*h2.x + e3*h3.x;
        a1 += e0*h0.y + e1*h1.y + e2*h2.y + e3*h3.y;
    }
    for (; j < end; j++) {
        int s = g_adj[j];
        float ex = __expf(lrelu(g_as2[s] + ad));
        float2 h = *(const float2*)(g_h2 + 2*s);
        z  += ex;
        a0 += ex * h.x;
        a1 += ex * h.y;
    }
    out[2*t]   = a0 / z + b2[0];
    out[2*t+1] = a1 / z + b2[1];
}

extern "C" void kernel_launch(void* const* d_in, const int* in_sizes, int n_in,
                              void* d_out, int out_size) {
    const float* x    = (const float*)d_in[0];
    const void*  ei   = d_in[1];
    const float* W1   = (const float*)d_in[2];
    const float* aS1  = (const float*)d_in[3];
    const float* aD1  = (const float*)d_in[4];
    const float* b1   = (const float*)d_in[5];
    const float* W2   = (const float*)d_in[6];
    const float* aS2  = (const float*)d_in[7];
    const float* aD2  = (const float*)d_in[8];
    const float* b2   = (const float*)d_in[9];
    float* out = (float*)d_out;

    // try to fork CSR build onto a second stream (hidden under cvt+mma);
    // fall back to fully serial default-stream launches if creation fails.
    cudaStream_t s1 = 0;
    cudaEvent_t evA = 0, evB = 0;
    bool par = (cudaStreamCreateWithFlags(&s1, cudaStreamNonBlocking) == cudaSuccess);
    if (par) par = (cudaEventCreateWithFlags(&evA, cudaEventDisableTiming) == cudaSuccess);
    if (par) par = (cudaEventCreateWithFlags(&evB, cudaEventDisableTiming) == cudaSuccess);
    cudaStream_t sb = par ? s1 : 0;

    const int TB = 256;
    k_zero<<<(N_NODES + TB - 1) / TB, TB>>>((const int*)ei);
    if (par) {
        cudaEventRecord(evA, 0);
        cudaStreamWaitEvent(s1, evA, 0);
    }
    // main stream: converts + tensor-core GEMM
    k_cvt<<<(CVT_X_CHUNKS + CVT_W_CHUNKS + TB - 1) / TB, TB>>>(x, W1);
    dim3 gg((N_NODES + 127) / 128, HH / 128);
    k_mma<<<gg, 256>>>(aS1, aD1);
    // side stream (or serial fallback): CSR build
    k_count<<<(N_EDGES + TB - 1) / TB, TB, 0, sb>>>(ei);
    k_scan1<<<NB, SCAN_BLK, 0, sb>>>();
    k_scan2<<<1, 128, 0, sb>>>();
    k_scan3<<<(N_NODES + TB - 1) / TB, TB, 0, sb>>>();
    k_fill<<<(ET + TB - 1) / TB, TB, 0, sb>>>(ei);
    if (par) {
        cudaEventRecord(evB, s1);
        cudaStreamWaitEvent(0, evB, 0);
    }
    k_fused1<<<(N_NODES*32 + TB - 1) / TB, TB>>>(b1, W2, aS2, aD2);
    k_fused2<<<(N_NODES + TB - 1) / TB, TB>>>(out, b2);
}